// round 9
// baseline (speedup 1.0000x reference)
#include <cuda_runtime.h>
#include <math.h>

// Problem constants
#define BB 64
#define TT 1024
#define DD 512
#define UU 1024
#define GG 4096           // 4*U
#define MM 65536          // B*T
#define NCTA 128          // persistent recurrent grid

// ---------------- scratch (static __device__, no allocs) ----------------
__device__ float g_xproj[(size_t)MM * GG];        // 1 GiB: x@Wx + bias, layout [t][b][g]
__device__ float g_hT[2][UU * BB];                // double-buffered hidden state, TRANSPOSED [u][b]
__device__ unsigned g_count;
__device__ unsigned g_release;

// phase-2 dynamic smem: Wh slice [1024][4 upair][4 gate][2] + dup h chunks [2][16][64] float2
#define WT_ELEMS (1024 * 32)
#define HS_F2    (2 * 16 * 64)                    // float2 elements
#define SMEM_RECUR ((WT_ELEMS + HS_F2 * 2) * 4)   // 147456 bytes

// ---------------- packed f32x2 FMA (Blackwell FFMA2, PTX-only) ----------------
__device__ __forceinline__ float2 ffma2(float2 a, float2 b, float2 c) {
    union U { float2 f; unsigned long long u; };
    U x, y, z, r;
    x.f = a; y.f = b; z.f = c;
    asm("fma.rn.f32x2 %0, %1, %2, %3;" : "=l"(r.u) : "l"(x.u), "l"(y.u), "l"(z.u));
    return r.f;
}

// fast transcendentals (MUFU-based, ~1e-6 rel err — threshold is 1e-3)
__device__ __forceinline__ float sigm(float x) { return 1.0f / (1.0f + __expf(-x)); }
__device__ __forceinline__ float tanh_f(float x) {
    return 1.0f - 2.0f / (__expf(2.0f * x) + 1.0f);
}

// ---------------- grid barrier (monotonic release, L2-coherent) ----------------
__device__ __forceinline__ void gridbar(unsigned s) {
    __syncthreads();
    if (threadIdx.x == 0) {
        __threadfence();
        unsigned prev = atomicAdd(&g_count, 1u);
        if (prev + 1u == (unsigned)NCTA * s) {
            atomicExch(&g_release, s);
        } else {
            volatile unsigned* rel = &g_release;
            while (*rel < s) { }
            __threadfence();
        }
    }
    __syncthreads();
}

// ---------------- init: zero h buffers + barrier state (runs every replay) ----------------
__global__ void k_init() {
    int i = blockIdx.x * blockDim.x + threadIdx.x;
    if (i < 2 * UU * BB) ((float*)g_hT)[i] = 0.0f;
    if (i == 0) { g_count = 0u; g_release = 0u; }
}

// no-op padding launches: shift k_recur to overall launch #6 so ncu (-s 5 -c 1)
// profiles the recurrent kernel instead of k_init.
__global__ void k_dummy() {}

// ---------------- phase 1: x_proj = inputs(65536x512) @ Wx(512x4096) + bias ----------------
// 128(m) x 64(n) tile, 256 threads, 8x4 microtile, f32x2 paired over m.
// Output written in recurrence-friendly layout [t][b][g].
__global__ __launch_bounds__(256) void k_xproj(const float* __restrict__ A,
                                               const float* __restrict__ W,
                                               const float* __restrict__ bias) {
    __shared__ float As[16][128];   // k-major
    __shared__ float Ws[16][64];    // n-major
    const int tid = threadIdx.x;
    const int m0 = blockIdx.y * 128;
    const int n0 = blockIdx.x * 64;
    const int ry8 = (tid >> 4) * 8;
    const int cx4 = (tid & 15) * 4;

    float2 acc[4][4];
#pragma unroll
    for (int i = 0; i < 4; i++)
#pragma unroll
        for (int j = 0; j < 4; j++) acc[i][j] = make_float2(0.f, 0.f);

#pragma unroll 1
    for (int kt = 0; kt < DD; kt += 16) {
#pragma unroll
        for (int i = 0; i < 2; i++) {
            int id = tid + i * 256;
            int r = id >> 2;
            int k4 = (id & 3) << 2;
            float4 v = *reinterpret_cast<const float4*>(A + (size_t)(m0 + r) * DD + kt + k4);
            As[k4 + 0][r] = v.x; As[k4 + 1][r] = v.y;
            As[k4 + 2][r] = v.z; As[k4 + 3][r] = v.w;
        }
        {
            int kr = tid >> 4;
            int nc = (tid & 15) << 2;
            *reinterpret_cast<float4*>(&Ws[kr][nc]) =
                *reinterpret_cast<const float4*>(W + (size_t)(kt + kr) * GG + n0 + nc);
        }
        __syncthreads();
#pragma unroll
        for (int kk = 0; kk < 16; kk++) {
            float4 a0 = *reinterpret_cast<const float4*>(&As[kk][ry8]);
            float4 a1 = *reinterpret_cast<const float4*>(&As[kk][ry8 + 4]);
            float4 bv = *reinterpret_cast<const float4*>(&Ws[kk][cx4]);
            float2 A2[4] = {{a0.x, a0.y}, {a0.z, a0.w}, {a1.x, a1.y}, {a1.z, a1.w}};
            float bb4[4] = {bv.x, bv.y, bv.z, bv.w};
#pragma unroll
            for (int mi = 0; mi < 4; mi++)
#pragma unroll
                for (int nj = 0; nj < 4; nj++)
                    acc[mi][nj] = ffma2(A2[mi], make_float2(bb4[nj], bb4[nj]), acc[mi][nj]);
        }
        __syncthreads();
    }

    float b4[4];
#pragma unroll
    for (int j = 0; j < 4; j++) b4[j] = bias[n0 + cx4 + j];
#pragma unroll
    for (int mi = 0; mi < 4; mi++) {
#pragma unroll
        for (int e = 0; e < 2; e++) {
            int m = m0 + ry8 + mi * 2 + e;
            int b = m >> 10;          // batch
            int t = m & 1023;         // time
            float4 o;
            o.x = (e ? acc[mi][0].y : acc[mi][0].x) + b4[0];
            o.y = (e ? acc[mi][1].y : acc[mi][1].x) + b4[1];
            o.z = (e ? acc[mi][2].y : acc[mi][2].x) + b4[2];
            o.w = (e ? acc[mi][3].y : acc[mi][3].x) + b4[3];
            *reinterpret_cast<float4*>(g_xproj + ((size_t)t * BB + b) * GG + n0 + cx4) = o;
        }
    }
}

// ---------------- phase 2: persistent recurrence, 128 CTAs x 256 threads ----------------
// CTA owns 8 units, full k=1024, Wh slice resident in SMEM (loaded once).
// Thread microtile: 1 batch x 2 units x 4 gates. ZERO-MOV f32x2:
//   - accumulator paired over the 2 units
//   - W unit-pairs come straight out of LDS.128 (aligned reg pairs)
//   - h broadcast operand pre-DUPLICATED in smem at stage time -> LDS.64 yields pair
// ONE grid barrier per step.
__global__ __launch_bounds__(256) void k_recur(const float* __restrict__ W,
                                               float* __restrict__ out) {
    extern __shared__ float smem[];
    float*  wt = smem;                                  // [1024][4 upair][4 gate][2]
    float2* hs = reinterpret_cast<float2*>(smem + WT_ELEMS);  // [2][16][64] duplicated h

    const int tid = threadIdx.x;
    const int cta = blockIdx.x;
    const int upair = tid & 3;          // 0..3
    const int b = tid >> 2;             // batch 0..63
    const int u0 = cta * 8 + upair * 2; // this thread's unit pair
    const float* Wh = W + (size_t)DD * GG;   // recurrent weights = kernel rows [512,1536)

    // ---- load this CTA's Wh slice into smem once: wt[k*32 + up*8 + gate*2 + e] ----
    for (int i = tid; i < WT_ELEMS; i += 256) {
        int e = i & 1;
        int gate = (i >> 1) & 3;
        int up = (i >> 3) & 3;
        int k = i >> 5;
        wt[i] = Wh[(size_t)k * GG + gate * UU + cta * 8 + up * 2 + e];
    }
    const float* wtp = wt + upair * 8;

    // stager indices (16 k-rows x 64 b per chunk, duplicate each value)
    const int skk = tid >> 4;           // 0..15
    const int sb4 = (tid & 15) << 2;    // 0..60

    float2 c = make_float2(0.f, 0.f);

    for (int step = 0; step < TT; ++step) {
        const int p = step & 1;
        const float* hin = g_hT[p];

        // ---- prefetch this step's xproj gate values (hidden under GEMM) ----
        const float* xrow = g_xproj + (size_t)step * (BB * GG) + (size_t)b * GG;
        float2 xp0 = __ldcg(reinterpret_cast<const float2*>(xrow + 0 * UU + u0));
        float2 xp1 = __ldcg(reinterpret_cast<const float2*>(xrow + 1 * UU + u0));
        float2 xp2 = __ldcg(reinterpret_cast<const float2*>(xrow + 2 * UU + u0));
        float2 xp3 = __ldcg(reinterpret_cast<const float2*>(xrow + 3 * UU + u0));

        float2 ai = make_float2(0.f, 0.f);
        float2 aj = make_float2(0.f, 0.f);
        float2 af = make_float2(0.f, 0.f);
        float2 ao = make_float2(0.f, 0.f);

        // ---- stage chunk 0 (duplicated) ----
        {
            float4 v = __ldcg(reinterpret_cast<const float4*>(hin + skk * 64 + sb4));
            float2* dst = hs + skk * 64 + sb4;
            *reinterpret_cast<float4*>(dst)     = make_float4(v.x, v.x, v.y, v.y);
            *reinterpret_cast<float4*>(dst + 2) = make_float4(v.z, v.z, v.w, v.w);
        }

        int cur = 0;
#pragma unroll 1
        for (int ch = 0; ch < 64; ch++) {
            __syncthreads();
            if (ch < 63) {
                float4 v = __ldcg(reinterpret_cast<const float4*>(
                    hin + (ch + 1) * 1024 + skk * 64 + sb4));
                float2* dst = hs + (cur ^ 1) * 1024 + skk * 64 + sb4;
                *reinterpret_cast<float4*>(dst)     = make_float4(v.x, v.x, v.y, v.y);
                *reinterpret_cast<float4*>(dst + 2) = make_float4(v.z, v.z, v.w, v.w);
            }
            const float2* hb = hs + cur * 1024;
            const float* wc = wtp + ch * 512;   // ch * 16 * 32
#pragma unroll
            for (int kk = 0; kk < 16; kk++) {
                float2 h2 = hb[kk * 64 + b];                                  // (h,h) pair
                float4 wa = *reinterpret_cast<const float4*>(wc + kk * 32);       // g0,g1
                float4 wb = *reinterpret_cast<const float4*>(wc + kk * 32 + 4);   // g2,g3
                ai = ffma2(h2, make_float2(wa.x, wa.y), ai);
                aj = ffma2(h2, make_float2(wa.z, wa.w), aj);
                af = ffma2(h2, make_float2(wb.x, wb.y), af);
                ao = ffma2(h2, make_float2(wb.z, wb.w), ao);
            }
            cur ^= 1;
        }

        // ---- cell update, fully register-local (2 units of batch b) ----
        float2 hv;
        {
            float i0 = ai.x + xp0.x, i1 = ai.y + xp0.y;
            float j0 = aj.x + xp1.x, j1 = aj.y + xp1.y;
            float f0 = af.x + xp2.x, f1 = af.y + xp2.y;
            float o0 = ao.x + xp3.x, o1 = ao.y + xp3.y;
            c.x = c.x * sigm(f0 + 1.0f) + sigm(i0) * tanh_f(j0);
            c.y = c.y * sigm(f1 + 1.0f) + sigm(i1) * tanh_f(j1);
            hv.x = tanh_f(c.x) * sigm(o0);
            hv.y = tanh_f(c.y) * sigm(o1);
        }

        // h^T write (cross-CTA visible), output write [b][t][u]
        __stcg(g_hT[p ^ 1] + (u0)     * 64 + b, hv.x);
        __stcg(g_hT[p ^ 1] + (u0 + 1) * 64 + b, hv.y);
        *reinterpret_cast<float2*>(out + (size_t)b * (TT * UU) + (size_t)step * UU + u0) = hv;

        gridbar(step + 1);
    }
}

// ---------------- launch ----------------
extern "C" void kernel_launch(void* const* d_in, const int* in_sizes, int n_in,
                              void* d_out, int out_size) {
    (void)in_sizes; (void)n_in; (void)out_size;
    const float* inputs = (const float*)d_in[0];
    const float* kern   = (const float*)d_in[1];
    const float* bias   = (const float*)d_in[2];
    float* out = (float*)d_out;

    cudaFuncSetAttribute(k_recur, cudaFuncAttributeMaxDynamicSharedMemorySize,
                         SMEM_RECUR);

    k_init<<<512, 256>>>();
    dim3 g1(GG / 64, MM / 128);   // (64, 512)
    k_xproj<<<g1, 256>>>(inputs, kern, bias);
    // padding so the 6th process-wide launch (ncu -s 5 -c 1) is k_recur
    k_dummy<<<1, 32>>>();
    k_dummy<<<1, 32>>>();
    k_dummy<<<1, 32>>>();
    k_recur<<<NCTA, 256, SMEM_RECUR>>>(kern, out);
}

// round 14
// speedup vs baseline: 3.0958x; 3.0958x over previous
#include <cuda_runtime.h>
#include <cuda_bf16.h>
#include <math.h>
#include <stdint.h>

// Problem constants
#define BB 64
#define TT 1024
#define DD 512
#define UU 1024
#define GG 4096           // 4*U
#define MM 65536          // B*T
#define NCTA 128          // persistent recurrent grid

// ---------------- scratch (static __device__, no allocs) ----------------
__device__ float g_xproj[(size_t)MM * GG];          // 1 GiB: x@Wx + bias, layout [t][b][g]
__device__ __nv_bfloat16 g_hbf[2][2][BB * UU];      // [buf][hi/lo][b*1024+k]
__device__ unsigned g_count;
__device__ unsigned g_release;

// ---------------- k_recur smem layout (bytes) ----------------
// W slices padded to 1032 bf16/row (2064B): 2064/16=129 ≡ 1 (mod 8) -> ldmatrix conflict-free
#define WPAD 1032
#define OFF_WHI 0
#define OFF_WLO (32 * WPAD * 2)                   // 66048
#define OFF_A   (OFF_WLO + 32 * WPAD * 2)         // 132096
#define APAD 72                                    // A row = 72 bf16 = 144B; 144/16=9 ≡ 1 (mod 8)
#define ASPLIT (64 * APAD * 2)                     // 9216 B per split
#define ABUF   (2 * ASPLIT)                        // 18432 B per buffer (hi+lo)
#define OFF_D  (OFF_A + 2 * ABUF)                  // 168960
#define SMEM_RECUR (OFF_D + 64 * 33 * 4)           // 177408 B

// ---------------- PTX helpers (all plain sm_80+ PTX, valid on sm_103) ----------------
__device__ __forceinline__ uint32_t smem_to_u32(const void* p) {
    uint32_t a;
    asm("{ .reg .u64 t; cvta.to.shared.u64 t, %1; cvt.u32.u64 %0, t; }" : "=r"(a) : "l"(p));
    return a;
}

__device__ __forceinline__ void cp_async16(uint32_t saddr, const void* gaddr) {
    asm volatile("cp.async.cg.shared.global [%0], [%1], 16;" :: "r"(saddr), "l"(gaddr));
}
#define CP_COMMIT() asm volatile("cp.async.commit_group;" ::: "memory")
#define CP_WAIT(n)  asm volatile("cp.async.wait_group %0;" :: "n"(n) : "memory")

__device__ __forceinline__ void ldmatrix_x4(uint32_t* r, uint32_t addr) {
    asm volatile("ldmatrix.sync.aligned.m8n8.x4.shared.b16 {%0,%1,%2,%3}, [%4];"
                 : "=r"(r[0]), "=r"(r[1]), "=r"(r[2]), "=r"(r[3]) : "r"(addr));
}

__device__ __forceinline__ void mma_bf16(float* d, const uint32_t* a, uint32_t b0, uint32_t b1) {
    asm volatile(
        "mma.sync.aligned.m16n8k16.row.col.f32.bf16.bf16.f32 "
        "{%0,%1,%2,%3}, {%4,%5,%6,%7}, {%8,%9}, {%0,%1,%2,%3};"
        : "+f"(d[0]), "+f"(d[1]), "+f"(d[2]), "+f"(d[3])
        : "r"(a[0]), "r"(a[1]), "r"(a[2]), "r"(a[3]), "r"(b0), "r"(b1));
}

// ---------------- misc math ----------------
__device__ __forceinline__ float2 ffma2(float2 a, float2 b, float2 c) {
    union U { float2 f; unsigned long long u; };
    U x, y, z, r;
    x.f = a; y.f = b; z.f = c;
    asm("fma.rn.f32x2 %0, %1, %2, %3;" : "=l"(r.u) : "l"(x.u), "l"(y.u), "l"(z.u));
    return r.f;
}
__device__ __forceinline__ float sigm(float x) { return 1.0f / (1.0f + __expf(-x)); }
__device__ __forceinline__ float tanh_f(float x) {
    return 1.0f - 2.0f / (__expf(2.0f * x) + 1.0f);
}

// ---------------- grid barrier (monotonic release, L2-coherent) ----------------
__device__ __forceinline__ void gridbar(unsigned s) {
    __syncthreads();
    if (threadIdx.x == 0) {
        __threadfence();
        unsigned prev = atomicAdd(&g_count, 1u);
        if (prev + 1u == (unsigned)NCTA * s) {
            atomicExch(&g_release, s);
        } else {
            volatile unsigned* rel = &g_release;
            while (*rel < s) { }
            __threadfence();
        }
    }
    __syncthreads();
}

// ---------------- init (runs every replay) ----------------
__global__ void k_init() {
    int i = blockIdx.x * blockDim.x + threadIdx.x;
    if (i < 131072) ((unsigned*)g_hbf)[i] = 0u;   // 512KB of bf16 zeros
    if (i == 0) { g_count = 0u; g_release = 0u; }
}

// ---------------- phase 1: x_proj (fp32 f32x2 SGEMM, unchanged from R1) ----------------
__global__ __launch_bounds__(256) void k_xproj(const float* __restrict__ A,
                                               const float* __restrict__ W,
                                               const float* __restrict__ bias) {
    __shared__ float As[16][128];
    __shared__ float Ws[16][64];
    const int tid = threadIdx.x;
    const int m0 = blockIdx.y * 128;
    const int n0 = blockIdx.x * 64;
    const int ry8 = (tid >> 4) * 8;
    const int cx4 = (tid & 15) * 4;

    float2 acc[4][4];
#pragma unroll
    for (int i = 0; i < 4; i++)
#pragma unroll
        for (int j = 0; j < 4; j++) acc[i][j] = make_float2(0.f, 0.f);

#pragma unroll 1
    for (int kt = 0; kt < DD; kt += 16) {
#pragma unroll
        for (int i = 0; i < 2; i++) {
            int id = tid + i * 256;
            int r = id >> 2;
            int k4 = (id & 3) << 2;
            float4 v = *reinterpret_cast<const float4*>(A + (size_t)(m0 + r) * DD + kt + k4);
            As[k4 + 0][r] = v.x; As[k4 + 1][r] = v.y;
            As[k4 + 2][r] = v.z; As[k4 + 3][r] = v.w;
        }
        {
            int kr = tid >> 4;
            int nc = (tid & 15) << 2;
            *reinterpret_cast<float4*>(&Ws[kr][nc]) =
                *reinterpret_cast<const float4*>(W + (size_t)(kt + kr) * GG + n0 + nc);
        }
        __syncthreads();
#pragma unroll
        for (int kk = 0; kk < 16; kk++) {
            float4 a0 = *reinterpret_cast<const float4*>(&As[kk][ry8]);
            float4 a1 = *reinterpret_cast<const float4*>(&As[kk][ry8 + 4]);
            float4 bv = *reinterpret_cast<const float4*>(&Ws[kk][cx4]);
            float2 A2[4] = {{a0.x, a0.y}, {a0.z, a0.w}, {a1.x, a1.y}, {a1.z, a1.w}};
            float bb4[4] = {bv.x, bv.y, bv.z, bv.w};
#pragma unroll
            for (int mi = 0; mi < 4; mi++)
#pragma unroll
                for (int nj = 0; nj < 4; nj++)
                    acc[mi][nj] = ffma2(A2[mi], make_float2(bb4[nj], bb4[nj]), acc[mi][nj]);
        }
        __syncthreads();
    }

    float b4[4];
#pragma unroll
    for (int j = 0; j < 4; j++) b4[j] = bias[n0 + cx4 + j];
#pragma unroll
    for (int mi = 0; mi < 4; mi++) {
#pragma unroll
        for (int e = 0; e < 2; e++) {
            int m = m0 + ry8 + mi * 2 + e;
            int b = m >> 10;
            int t = m & 1023;
            float4 o;
            o.x = (e ? acc[mi][0].y : acc[mi][0].x) + b4[0];
            o.y = (e ? acc[mi][1].y : acc[mi][1].x) + b4[1];
            o.z = (e ? acc[mi][2].y : acc[mi][2].x) + b4[2];
            o.w = (e ? acc[mi][3].y : acc[mi][3].x) + b4[3];
            *reinterpret_cast<float4*>(g_xproj + ((size_t)t * BB + b) * GG + n0 + cx4) = o;
        }
    }
}

// ---------------- phase 2: persistent mma.sync recurrence ----------------
// 128 CTAs x 256 threads (8 warps). CTA owns 8 units = 32 gate-cols, M=64 batch, K=1024.
// hi/lo bf16 split of h and Wh; 3 mma passes (hh, hl, lh); fp32 accumulate in registers.
// W_hi/W_lo resident in smem. h staged per 64-k chunk via cp.async, double-buffered.
// One grid barrier per step.
__global__ __launch_bounds__(256) void k_recur(const float* __restrict__ W,
                                               float* __restrict__ out) {
    extern __shared__ char sm[];
    const uint32_t smb = smem_to_u32(sm);
    const int tid = threadIdx.x;
    const int wid = tid >> 5;
    const int lid = tid & 31;
    const int cta = blockIdx.x;
    const float* Wh = W + (size_t)DD * GG;   // recurrent weights rows [512,1536)

    // ---- load W hi/lo split into smem (once): whsm[n][k], n = gate*8 + uo ----
    {
        __nv_bfloat16* whi = reinterpret_cast<__nv_bfloat16*>(sm + OFF_WHI);
        __nv_bfloat16* wlo = reinterpret_cast<__nv_bfloat16*>(sm + OFF_WLO);
        for (int i = tid; i < 32 * 1024; i += 256) {
            int k = i & 1023;
            int n = i >> 10;
            int col = (n >> 3) * UU + cta * 8 + (n & 7);
            float w = Wh[(size_t)k * GG + col];
            __nv_bfloat16 hi = __float2bfloat16(w);
            __nv_bfloat16 lo = __float2bfloat16(w - __bfloat162float(hi));
            whi[n * WPAD + k] = hi;
            wlo[n * WPAD + k] = lo;
        }
    }
    __syncthreads();

    // ---- warp tiling: 4 m-tiles x 2 n-halves ----
    const int wm = wid >> 1;            // m-tile 0..3 (rows wm*16)
    const int wn = wid & 1;             // n-half 0..1 (cols wn*16)

    // ldmatrix lane addresses (canonical TN non-trans fragments)
    const int a_row  = wm * 16 + (lid & 15);
    const int a_koff = (lid >> 4) * 8;                          // bf16 units
    const uint32_t a_lane = smb + OFF_A + (uint32_t)(a_row * (APAD * 2) + a_koff * 2);
    const int b_row  = wn * 16 + (lid & 7) + ((lid >> 4) << 3);
    const int b_koff = ((lid >> 3) & 1) * 8;
    const uint32_t bhi_lane = smb + OFF_WHI + (uint32_t)(b_row * (WPAD * 2) + b_koff * 2);
    const uint32_t blo_lane = smb + OFF_WLO + (uint32_t)(b_row * (WPAD * 2) + b_koff * 2);

    // staging map: 256 threads cover [2 splits][64 rows][64 k] per chunk, 4x16B each
    const int s_split = tid >> 7;                // 0:hi 1:lo
    const int s_row   = (tid & 127) >> 1;        // 0..63 (batch)
    const int s_half  = (tid & 1) * 32;          // bf16 offset within 64-k chunk
    const uint32_t s_sm = smb + OFF_A + (uint32_t)(s_split * ASPLIT +
                           s_row * (APAD * 2) + s_half * 2);

    // cell map: thread = (b, q), 2 units q*2, q*2+1
    const int b  = tid >> 2;
    const int q  = tid & 3;
    const int ub = q * 2;
    const int ug = cta * 8 + ub;
    float* Dsm = reinterpret_cast<float*>(sm + OFF_D);    // [64][33]

    float2 c = make_float2(0.f, 0.f);

    for (int step = 0; step < TT; ++step) {
        const int p = step & 1;

        // prefetch xproj gates for this thread's 2 cells
        const float* xrow = g_xproj + (size_t)step * (BB * GG) + (size_t)b * GG;
        float2 xp0 = __ldcg(reinterpret_cast<const float2*>(xrow + 0 * UU + ug));
        float2 xp1 = __ldcg(reinterpret_cast<const float2*>(xrow + 1 * UU + ug));
        float2 xp2 = __ldcg(reinterpret_cast<const float2*>(xrow + 2 * UU + ug));
        float2 xp3 = __ldcg(reinterpret_cast<const float2*>(xrow + 3 * UU + ug));

        const __nv_bfloat16* hsrc = g_hbf[p][s_split] + (s_row << 10) + s_half;

        float acc0[4] = {0.f, 0.f, 0.f, 0.f};   // n-tile 0 (cols wn*16 + 0..7)
        float acc1[4] = {0.f, 0.f, 0.f, 0.f};   // n-tile 1 (cols wn*16 + 8..15)

        // stage chunk 0
#pragma unroll
        for (int c4 = 0; c4 < 4; c4++)
            cp_async16(s_sm + c4 * 16, hsrc + c4 * 8);
        CP_COMMIT();

#pragma unroll 1
        for (int kt = 0; kt < 16; kt++) {
            if (kt < 15) {
                const uint32_t dst = s_sm + (uint32_t)(((kt + 1) & 1) * ABUF);
                const __nv_bfloat16* src = hsrc + (kt + 1) * 64;
#pragma unroll
                for (int c4 = 0; c4 < 4; c4++)
                    cp_async16(dst + c4 * 16, src + c4 * 8);
                CP_COMMIT();
                CP_WAIT(1);
            } else {
                CP_WAIT(0);
            }
            __syncthreads();

            const uint32_t abase = a_lane + (uint32_t)((kt & 1) * ABUF);
            const uint32_t bkoff = (uint32_t)(kt * 128);   // kt*64 bf16 * 2B
#pragma unroll
            for (int ks = 0; ks < 4; ks++) {
                uint32_t ah[4], al[4], bh[4], bl[4];
                ldmatrix_x4(ah, abase + ks * 32);
                ldmatrix_x4(al, abase + ASPLIT + ks * 32);
                ldmatrix_x4(bh, bhi_lane + bkoff + ks * 32);
                ldmatrix_x4(bl, blo_lane + bkoff + ks * 32);
                mma_bf16(acc0, ah, bh[0], bh[1]);
                mma_bf16(acc1, ah, bh[2], bh[3]);
                mma_bf16(acc0, ah, bl[0], bl[1]);
                mma_bf16(acc1, ah, bl[2], bl[3]);
                mma_bf16(acc0, al, bh[0], bh[1]);
                mma_bf16(acc1, al, bh[2], bh[3]);
            }
            __syncthreads();
        }

        // ---- dump accumulators to smem gates buffer ----
        {
            int r0 = wm * 16 + (lid >> 2);
            int c0 = wn * 16 + (lid & 3) * 2;
            Dsm[r0 * 33 + c0]           = acc0[0];
            Dsm[r0 * 33 + c0 + 1]       = acc0[1];
            Dsm[(r0 + 8) * 33 + c0]     = acc0[2];
            Dsm[(r0 + 8) * 33 + c0 + 1] = acc0[3];
            Dsm[r0 * 33 + c0 + 8]           = acc1[0];
            Dsm[r0 * 33 + c0 + 9]           = acc1[1];
            Dsm[(r0 + 8) * 33 + c0 + 8]     = acc1[2];
            Dsm[(r0 + 8) * 33 + c0 + 9]     = acc1[3];
        }
        __syncthreads();

        // ---- register-local cell update ----
        float2 hv;
        {
            const float* d0 = Dsm + b * 33;
            float i0 = d0[ub]      + xp0.x,  i1 = d0[ub + 1]  + xp0.y;
            float j0 = d0[8 + ub]  + xp1.x,  j1 = d0[9 + ub]  + xp1.y;
            float f0 = d0[16 + ub] + xp2.x,  f1 = d0[17 + ub] + xp2.y;
            float o0 = d0[24 + ub] + xp3.x,  o1 = d0[25 + ub] + xp3.y;
            c.x = c.x * sigm(f0 + 1.0f) + sigm(i0) * tanh_f(j0);
            c.y = c.y * sigm(f1 + 1.0f) + sigm(i1) * tanh_f(j1);
            hv.x = tanh_f(c.x) * sigm(o0);
            hv.y = tanh_f(c.y) * sigm(o1);
        }

        // ---- write split h (bf16 hi/lo) + fp32 output ----
        {
            __nv_bfloat16 h0h = __float2bfloat16(hv.x);
            __nv_bfloat16 h1h = __float2bfloat16(hv.y);
            __nv_bfloat16 h0l = __float2bfloat16(hv.x - __bfloat162float(h0h));
            __nv_bfloat16 h1l = __float2bfloat16(hv.y - __bfloat162float(h1h));
            unsigned phi = (unsigned)__bfloat16_as_ushort(h0h) |
                           ((unsigned)__bfloat16_as_ushort(h1h) << 16);
            unsigned plo = (unsigned)__bfloat16_as_ushort(h0l) |
                           ((unsigned)__bfloat16_as_ushort(h1l) << 16);
            __stcg(reinterpret_cast<unsigned*>(&g_hbf[p ^ 1][0][(b << 10) + ug]), phi);
            __stcg(reinterpret_cast<unsigned*>(&g_hbf[p ^ 1][1][(b << 10) + ug]), plo);
            *reinterpret_cast<float2*>(out + (size_t)b * (TT * UU) + (size_t)step * UU + ug) = hv;
        }

        gridbar(step + 1);
    }
}

// ---------------- launch ----------------
extern "C" void kernel_launch(void* const* d_in, const int* in_sizes, int n_in,
                              void* d_out, int out_size) {
    (void)in_sizes; (void)n_in; (void)out_size;
    const float* inputs = (const float*)d_in[0];
    const float* kern   = (const float*)d_in[1];
    const float* bias   = (const float*)d_in[2];
    float* out = (float*)d_out;

    cudaFuncSetAttribute(k_recur, cudaFuncAttributeMaxDynamicSharedMemorySize, SMEM_RECUR);

    k_init<<<512, 256>>>();
    dim3 g1(GG / 64, MM / 128);   // (64, 512)
    k_xproj<<<g1, 256>>>(inputs, kern, bias);
    k_recur<<<NCTA, 256, SMEM_RECUR>>>(kern, out);
}

// round 15
// speedup vs baseline: 3.3426x; 1.0797x over previous
#include <cuda_runtime.h>
#include <cuda_bf16.h>
#include <math.h>
#include <stdint.h>

// Problem constants
#define BB 64
#define TT 1024
#define DD 512
#define UU 1024
#define GG 4096           // 4*U
#define MM 65536          // B*T
#define NCTA 128          // persistent recurrent grid

// ---------------- scratch (static __device__, no allocs) ----------------
__device__ float g_xproj[(size_t)MM * GG];          // 1 GiB: x@Wx + bias, layout [t][b][g]
__device__ __nv_bfloat16 g_xhi[(size_t)MM * DD];    // 64MB X hi split [m][k]
__device__ __nv_bfloat16 g_xlo[(size_t)MM * DD];    // 64MB X lo split
__device__ __nv_bfloat16 g_whi[(size_t)GG * DD];    // 4MB Wx^T hi [n][k]
__device__ __nv_bfloat16 g_wlo[(size_t)GG * DD];    // 4MB Wx^T lo
__device__ __nv_bfloat16 g_hbf[2][2][BB * UU];      // [buf][hi/lo][b*1024+k]
__device__ unsigned g_count;
__device__ unsigned g_release;

// ---------------- k_recur smem layout (bytes) ----------------
// W slices padded to 1032 bf16/row (2064B): 2064/16=129 ≡ 1 (mod 8) -> ldmatrix conflict-free
#define WPAD 1032
#define OFF_WHI 0
#define OFF_WLO (32 * WPAD * 2)                   // 66048
#define OFF_A   (OFF_WLO + 32 * WPAD * 2)         // 132096
#define APAD 72                                    // A row = 144B; 144/16=9 ≡ 1 (mod 8)
#define ASPLIT (64 * APAD * 2)                     // 9216 B per split
#define ABUF   (2 * ASPLIT)                        // 18432 B per buffer (hi+lo); 3 buffers
#define OFF_D  (OFF_A + 3 * ABUF)                  // 187392
#define SMEM_RECUR (OFF_D + 64 * 33 * 4)           // 195840 B

// ---------------- k_xproj_mma smem layout ----------------
#define XAPAD 40                                   // 80B row stride; 80/16=5 ≡ 5 (mod 8) OK
#define XA_SPLIT (128 * XAPAD * 2)                 // 10240
#define XA_BUF (2 * XA_SPLIT)                      // 20480 (hi+lo)
#define XB_SPLIT (64 * XAPAD * 2)                  // 5120
#define XB_BUF (2 * XB_SPLIT)                      // 10240
#define XOFF_A 0
#define XOFF_B (3 * XA_BUF)                        // 61440
#define XSMEM (XOFF_B + 3 * XB_BUF)                // 92160

// ---------------- PTX helpers (plain sm_80+ PTX, valid on sm_103) ----------------
__device__ __forceinline__ uint32_t smem_to_u32(const void* p) {
    uint32_t a;
    asm("{ .reg .u64 t; cvta.to.shared.u64 t, %1; cvt.u32.u64 %0, t; }" : "=r"(a) : "l"(p));
    return a;
}

__device__ __forceinline__ void cp_async16(uint32_t saddr, const void* gaddr) {
    asm volatile("cp.async.cg.shared.global [%0], [%1], 16;" :: "r"(saddr), "l"(gaddr));
}
#define CP_COMMIT() asm volatile("cp.async.commit_group;" ::: "memory")
#define CP_WAIT(n)  asm volatile("cp.async.wait_group %0;" :: "n"(n) : "memory")

__device__ __forceinline__ void ldmatrix_x4(uint32_t* r, uint32_t addr) {
    asm volatile("ldmatrix.sync.aligned.m8n8.x4.shared.b16 {%0,%1,%2,%3}, [%4];"
                 : "=r"(r[0]), "=r"(r[1]), "=r"(r[2]), "=r"(r[3]) : "r"(addr));
}

__device__ __forceinline__ void mma_bf16(float* d, const uint32_t* a, uint32_t b0, uint32_t b1) {
    asm volatile(
        "mma.sync.aligned.m16n8k16.row.col.f32.bf16.bf16.f32 "
        "{%0,%1,%2,%3}, {%4,%5,%6,%7}, {%8,%9}, {%0,%1,%2,%3};"
        : "+f"(d[0]), "+f"(d[1]), "+f"(d[2]), "+f"(d[3])
        : "r"(a[0]), "r"(a[1]), "r"(a[2]), "r"(a[3]), "r"(b0), "r"(b1));
}

// ---------------- misc math ----------------
__device__ __forceinline__ float sigm(float x) { return 1.0f / (1.0f + __expf(-x)); }
__device__ __forceinline__ float tanh_f(float x) {
    return 1.0f - 2.0f / (__expf(2.0f * x) + 1.0f);
}

// ---------------- grid barrier (monotonic release, L2-coherent) ----------------
__device__ __forceinline__ void gridbar(unsigned s) {
    __syncthreads();
    if (threadIdx.x == 0) {
        __threadfence();
        unsigned prev = atomicAdd(&g_count, 1u);
        if (prev + 1u == (unsigned)NCTA * s) {
            atomicExch(&g_release, s);
        } else {
            volatile unsigned* rel = &g_release;
            while (*rel < s) { }
            __threadfence();
        }
    }
    __syncthreads();
}

// ---------------- init (runs every replay) ----------------
__global__ void k_init() {
    int i = blockIdx.x * blockDim.x + threadIdx.x;
    if (i < 131072) ((unsigned*)g_hbf)[i] = 0u;   // 512KB of bf16 zeros
    if (i == 0) { g_count = 0u; g_release = 0u; }
}

__global__ void k_dummy() {}

// ---------------- prepass A: split X fp32 -> bf16 hi/lo, layout [m][k] ----------------
__global__ __launch_bounds__(256) void k_split_x(const float* __restrict__ X) {
    int idx = blockIdx.x * 256 + threadIdx.x;          // 4194304 threads, 8 elems each
    const float* src = X + (size_t)idx * 8;
    float4 v0 = *reinterpret_cast<const float4*>(src);
    float4 v1 = *reinterpret_cast<const float4*>(src + 4);
    float f[8] = {v0.x, v0.y, v0.z, v0.w, v1.x, v1.y, v1.z, v1.w};
    unsigned hi[4], lo[4];
#pragma unroll
    for (int i = 0; i < 4; i++) {
        __nv_bfloat16 h0 = __float2bfloat16(f[2 * i]);
        __nv_bfloat16 h1 = __float2bfloat16(f[2 * i + 1]);
        __nv_bfloat16 l0 = __float2bfloat16(f[2 * i]     - __bfloat162float(h0));
        __nv_bfloat16 l1 = __float2bfloat16(f[2 * i + 1] - __bfloat162float(h1));
        hi[i] = (unsigned)__bfloat16_as_ushort(h0) | ((unsigned)__bfloat16_as_ushort(h1) << 16);
        lo[i] = (unsigned)__bfloat16_as_ushort(l0) | ((unsigned)__bfloat16_as_ushort(l1) << 16);
    }
    *reinterpret_cast<uint4*>(g_xhi + (size_t)idx * 8) = make_uint4(hi[0], hi[1], hi[2], hi[3]);
    *reinterpret_cast<uint4*>(g_xlo + (size_t)idx * 8) = make_uint4(lo[0], lo[1], lo[2], lo[3]);
}

// ---------------- prepass B: transpose+split Wx[k][n] -> [n][k] bf16 hi/lo ----------------
__global__ __launch_bounds__(256) void k_split_w(const float* __restrict__ Wx) {
    __shared__ float ts[32][33];
    const int n0 = blockIdx.x * 32;
    const int k0 = blockIdx.y * 32;
    const int c = threadIdx.x & 31;
    const int rw = threadIdx.x >> 5;
#pragma unroll
    for (int rr = 0; rr < 4; rr++) {
        int r = rw + rr * 8;
        ts[r][c] = Wx[(size_t)(k0 + r) * GG + n0 + c];
    }
    __syncthreads();
#pragma unroll
    for (int rr = 0; rr < 4; rr++) {
        int r = rw + rr * 8;                // output n-row within tile
        float v = ts[c][r];
        __nv_bfloat16 h = __float2bfloat16(v);
        __nv_bfloat16 l = __float2bfloat16(v - __bfloat162float(h));
        g_whi[(size_t)(n0 + r) * DD + k0 + c] = h;
        g_wlo[(size_t)(n0 + r) * DD + k0 + c] = l;
    }
}

// ---------------- phase 1: x_proj via mma.sync (hi/lo 3-pass) ----------------
// CTA: 128m x 64n, K=512 in 16 chunks of 32. 8 warps: (wid>>1)=m-tile of 32, (wid&1)=n-half of 32.
// 3-stage cp.async pipeline, one syncthreads per chunk.
__global__ __launch_bounds__(256) void k_xproj_mma(const float* __restrict__ bias) {
    extern __shared__ char sm[];
    const uint32_t smb = smem_to_u32(sm);
    const int tid = threadIdx.x;
    const int wid = tid >> 5;
    const int lid = tid & 31;
    const int m0 = blockIdx.y * 128;
    const int n0 = blockIdx.x * 64;
    const int wm = wid >> 1;
    const int wn = wid & 1;

    // staging maps
    const int sa_split = tid >> 7;                 // 0:hi 1:lo
    const int sa_row   = tid & 127;
    const __nv_bfloat16* xsrc = (sa_split ? g_xlo : g_xhi) + (size_t)(m0 + sa_row) * DD;
    const uint32_t sa_dst = smb + XOFF_A + (uint32_t)(sa_split * XA_SPLIT + sa_row * (XAPAD * 2));
    const int sb_split = (tid >> 6) & 1;
    const int sb_row   = tid & 63;
    const __nv_bfloat16* wsrc = (sb_split ? g_wlo : g_whi) + (size_t)(n0 + sb_row) * DD;
    const uint32_t sb_dst = smb + XOFF_B + (uint32_t)(sb_split * XB_SPLIT + sb_row * (XAPAD * 2));

    // fragment lane addresses
    const uint32_t a_lane0 = smb + XOFF_A +
        (uint32_t)((wm * 32 + (lid & 15)) * (XAPAD * 2) + ((lid >> 4) * 8) * 2);
    const uint32_t a_lane1 = a_lane0 + (uint32_t)(16 * (XAPAD * 2));
    const uint32_t b_lane0 = smb + XOFF_B +
        (uint32_t)((wn * 32 + (lid & 7) + ((lid >> 4) << 3)) * (XAPAD * 2) + (((lid >> 3) & 1) * 8) * 2);
    const uint32_t b_lane1 = b_lane0 + (uint32_t)(16 * (XAPAD * 2));

    float acc[2][4][4];
#pragma unroll
    for (int a = 0; a < 2; a++)
#pragma unroll
        for (int j = 0; j < 4; j++)
#pragma unroll
            for (int e = 0; e < 4; e++) acc[a][j][e] = 0.f;

    auto stage = [&](int ck) {
        const uint32_t da = sa_dst + (uint32_t)((ck % 3) * XA_BUF);
        const __nv_bfloat16* s = xsrc + ck * 32;
#pragma unroll
        for (int c4 = 0; c4 < 4; c4++) cp_async16(da + c4 * 16, s + c4 * 8);
        if (tid < 128) {
            const uint32_t db = sb_dst + (uint32_t)((ck % 3) * XB_BUF);
            const __nv_bfloat16* sb = wsrc + ck * 32;
#pragma unroll
            for (int c4 = 0; c4 < 4; c4++) cp_async16(db + c4 * 16, sb + c4 * 8);
        }
        CP_COMMIT();
    };

    stage(0);
    stage(1);

#pragma unroll 1
    for (int kc = 0; kc < 16; kc++) {
        if (kc < 15) { CP_WAIT(1); } else { CP_WAIT(0); }
        __syncthreads();
        if (kc < 14) stage(kc + 2);

        const uint32_t aoff = (uint32_t)((kc % 3) * XA_BUF);
        const uint32_t boff = (uint32_t)((kc % 3) * XB_BUF);
#pragma unroll
        for (int ks = 0; ks < 2; ks++) {
            uint32_t ah0[4], ah1[4], al0[4], al1[4];
            uint32_t bh0[4], bh1[4], bl0[4], bl1[4];
            ldmatrix_x4(ah0, a_lane0 + aoff + ks * 32);
            ldmatrix_x4(ah1, a_lane1 + aoff + ks * 32);
            ldmatrix_x4(al0, a_lane0 + aoff + XA_SPLIT + ks * 32);
            ldmatrix_x4(al1, a_lane1 + aoff + XA_SPLIT + ks * 32);
            ldmatrix_x4(bh0, b_lane0 + boff + ks * 32);
            ldmatrix_x4(bh1, b_lane1 + boff + ks * 32);
            ldmatrix_x4(bl0, b_lane0 + boff + XB_SPLIT + ks * 32);
            ldmatrix_x4(bl1, b_lane1 + boff + XB_SPLIT + ks * 32);
            // pass hh
            mma_bf16(acc[0][0], ah0, bh0[0], bh0[1]); mma_bf16(acc[0][1], ah0, bh0[2], bh0[3]);
            mma_bf16(acc[0][2], ah0, bh1[0], bh1[1]); mma_bf16(acc[0][3], ah0, bh1[2], bh1[3]);
            mma_bf16(acc[1][0], ah1, bh0[0], bh0[1]); mma_bf16(acc[1][1], ah1, bh0[2], bh0[3]);
            mma_bf16(acc[1][2], ah1, bh1[0], bh1[1]); mma_bf16(acc[1][3], ah1, bh1[2], bh1[3]);
            // pass hl (Xhi x Wlo)
            mma_bf16(acc[0][0], ah0, bl0[0], bl0[1]); mma_bf16(acc[0][1], ah0, bl0[2], bl0[3]);
            mma_bf16(acc[0][2], ah0, bl1[0], bl1[1]); mma_bf16(acc[0][3], ah0, bl1[2], bl1[3]);
            mma_bf16(acc[1][0], ah1, bl0[0], bl0[1]); mma_bf16(acc[1][1], ah1, bl0[2], bl0[3]);
            mma_bf16(acc[1][2], ah1, bl1[0], bl1[1]); mma_bf16(acc[1][3], ah1, bl1[2], bl1[3]);
            // pass lh (Xlo x Whi)
            mma_bf16(acc[0][0], al0, bh0[0], bh0[1]); mma_bf16(acc[0][1], al0, bh0[2], bh0[3]);
            mma_bf16(acc[0][2], al0, bh1[0], bh1[1]); mma_bf16(acc[0][3], al0, bh1[2], bh1[3]);
            mma_bf16(acc[1][0], al1, bh0[0], bh0[1]); mma_bf16(acc[1][1], al1, bh0[2], bh0[3]);
            mma_bf16(acc[1][2], al1, bh1[0], bh1[1]); mma_bf16(acc[1][3], al1, bh1[2], bh1[3]);
        }
    }

    // epilogue: bias add + store fp32 to g_xproj[t][b][g]
    const int er = lid >> 2;
    const int ec = (lid & 3) * 2;
#pragma unroll
    for (int mt = 0; mt < 2; mt++) {
        int mr = m0 + wm * 32 + mt * 16 + er;
#pragma unroll
        for (int j = 0; j < 4; j++) {
            int n = n0 + wn * 32 + j * 8 + ec;
            float2 bv = *reinterpret_cast<const float2*>(bias + n);
            int b0i = mr >> 10, t0i = mr & 1023;
            int b1i = (mr + 8) >> 10, t1i = (mr + 8) & 1023;
            float2 o0 = make_float2(acc[mt][j][0] + bv.x, acc[mt][j][1] + bv.y);
            float2 o1 = make_float2(acc[mt][j][2] + bv.x, acc[mt][j][3] + bv.y);
            *reinterpret_cast<float2*>(g_xproj + ((size_t)t0i * BB + b0i) * GG + n) = o0;
            *reinterpret_cast<float2*>(g_xproj + ((size_t)t1i * BB + b1i) * GG + n) = o1;
        }
    }
}

// ---------------- phase 2: persistent mma.sync recurrence ----------------
// 128 CTAs x 256 threads (8 warps). CTA owns 8 units = 32 gate-cols, M=64 batch, K=1024.
// hi/lo bf16 split; 3 mma passes; fp32 accumulate. W resident in smem.
// h staged per 64-k chunk via cp.async, 3-stage pipeline, ONE syncthreads per chunk.
// One grid barrier per step.
__global__ __launch_bounds__(256) void k_recur(const float* __restrict__ W,
                                               float* __restrict__ out) {
    extern __shared__ char sm[];
    const uint32_t smb = smem_to_u32(sm);
    const int tid = threadIdx.x;
    const int wid = tid >> 5;
    const int lid = tid & 31;
    const int cta = blockIdx.x;
    const float* Wh = W + (size_t)DD * GG;   // recurrent weights rows [512,1536)

    // ---- load W hi/lo split into smem (once): whsm[n][k], n = gate*8 + uo ----
    {
        __nv_bfloat16* whi = reinterpret_cast<__nv_bfloat16*>(sm + OFF_WHI);
        __nv_bfloat16* wlo = reinterpret_cast<__nv_bfloat16*>(sm + OFF_WLO);
        for (int i = tid; i < 32 * 1024; i += 256) {
            int k = i & 1023;
            int n = i >> 10;
            int col = (n >> 3) * UU + cta * 8 + (n & 7);
            float w = Wh[(size_t)k * GG + col];
            __nv_bfloat16 hi = __float2bfloat16(w);
            __nv_bfloat16 lo = __float2bfloat16(w - __bfloat162float(hi));
            whi[n * WPAD + k] = hi;
            wlo[n * WPAD + k] = lo;
        }
    }
    __syncthreads();

    // ---- warp tiling: 4 m-tiles x 2 n-halves ----
    const int wm = wid >> 1;
    const int wn = wid & 1;

    const int a_row  = wm * 16 + (lid & 15);
    const int a_koff = (lid >> 4) * 8;
    const uint32_t a_lane = smb + OFF_A + (uint32_t)(a_row * (APAD * 2) + a_koff * 2);
    const int b_row  = wn * 16 + (lid & 7) + ((lid >> 4) << 3);
    const int b_koff = ((lid >> 3) & 1) * 8;
    const uint32_t bhi_lane = smb + OFF_WHI + (uint32_t)(b_row * (WPAD * 2) + b_koff * 2);
    const uint32_t blo_lane = smb + OFF_WLO + (uint32_t)(b_row * (WPAD * 2) + b_koff * 2);

    // staging map: 256 threads cover [2 splits][64 rows][64 k] per chunk, 4x16B each
    const int s_split = tid >> 7;
    const int s_row   = (tid & 127) >> 1;
    const int s_half  = (tid & 1) * 32;
    const uint32_t s_sm = smb + OFF_A + (uint32_t)(s_split * ASPLIT +
                           s_row * (APAD * 2) + s_half * 2);

    // cell map: thread = (b, q), 2 units q*2, q*2+1
    const int b  = tid >> 2;
    const int q  = tid & 3;
    const int ub = q * 2;
    const int ug = cta * 8 + ub;
    float* Dsm = reinterpret_cast<float*>(sm + OFF_D);    // [64][33]

    float2 c = make_float2(0.f, 0.f);

    for (int step = 0; step < TT; ++step) {
        const int p = step & 1;

        // prefetch xproj gates for this thread's 2 cells
        const float* xrow = g_xproj + (size_t)step * (BB * GG) + (size_t)b * GG;
        float2 xp0 = __ldcg(reinterpret_cast<const float2*>(xrow + 0 * UU + ug));
        float2 xp1 = __ldcg(reinterpret_cast<const float2*>(xrow + 1 * UU + ug));
        float2 xp2 = __ldcg(reinterpret_cast<const float2*>(xrow + 2 * UU + ug));
        float2 xp3 = __ldcg(reinterpret_cast<const float2*>(xrow + 3 * UU + ug));

        const __nv_bfloat16* hsrc = g_hbf[p][s_split] + (s_row << 10) + s_half;

        float acc0[4] = {0.f, 0.f, 0.f, 0.f};
        float acc1[4] = {0.f, 0.f, 0.f, 0.f};

        // 3-stage pipeline prologue
        {
#pragma unroll
            for (int c4 = 0; c4 < 4; c4++) cp_async16(s_sm + c4 * 16, hsrc + c4 * 8);
            CP_COMMIT();
            const uint32_t d1 = s_sm + ABUF;
#pragma unroll
            for (int c4 = 0; c4 < 4; c4++) cp_async16(d1 + c4 * 16, hsrc + 64 + c4 * 8);
            CP_COMMIT();
        }

#pragma unroll 1
        for (int kt = 0; kt < 16; kt++) {
            if (kt < 15) { CP_WAIT(1); } else { CP_WAIT(0); }
            __syncthreads();
            if (kt < 14) {
                const uint32_t dst = s_sm + (uint32_t)(((kt + 2) % 3) * ABUF);
                const __nv_bfloat16* src = hsrc + (kt + 2) * 64;
#pragma unroll
                for (int c4 = 0; c4 < 4; c4++) cp_async16(dst + c4 * 16, src + c4 * 8);
                CP_COMMIT();
            }

            const uint32_t abase = a_lane + (uint32_t)((kt % 3) * ABUF);
            const uint32_t bkoff = (uint32_t)(kt * 128);
#pragma unroll
            for (int ks = 0; ks < 4; ks++) {
                uint32_t ah[4], al[4], bh[4], bl[4];
                ldmatrix_x4(ah, abase + ks * 32);
                ldmatrix_x4(al, abase + ASPLIT + ks * 32);
                ldmatrix_x4(bh, bhi_lane + bkoff + ks * 32);
                ldmatrix_x4(bl, blo_lane + bkoff + ks * 32);
                mma_bf16(acc0, ah, bh[0], bh[1]);
                mma_bf16(acc1, ah, bh[2], bh[3]);
                mma_bf16(acc0, ah, bl[0], bl[1]);
                mma_bf16(acc1, ah, bl[2], bl[3]);
                mma_bf16(acc0, al, bh[0], bh[1]);
                mma_bf16(acc1, al, bh[2], bh[3]);
            }
        }

        // ---- dump accumulators to smem gates buffer ----
        {
            int r0 = wm * 16 + (lid >> 2);
            int c0 = wn * 16 + (lid & 3) * 2;
            Dsm[r0 * 33 + c0]           = acc0[0];
            Dsm[r0 * 33 + c0 + 1]       = acc0[1];
            Dsm[(r0 + 8) * 33 + c0]     = acc0[2];
            Dsm[(r0 + 8) * 33 + c0 + 1] = acc0[3];
            Dsm[r0 * 33 + c0 + 8]           = acc1[0];
            Dsm[r0 * 33 + c0 + 9]           = acc1[1];
            Dsm[(r0 + 8) * 33 + c0 + 8]     = acc1[2];
            Dsm[(r0 + 8) * 33 + c0 + 9]     = acc1[3];
        }
        __syncthreads();

        // ---- register-local cell update ----
        float2 hv;
        {
            const float* d0 = Dsm + b * 33;
            float i0 = d0[ub]      + xp0.x,  i1 = d0[ub + 1]  + xp0.y;
            float j0 = d0[8 + ub]  + xp1.x,  j1 = d0[9 + ub]  + xp1.y;
            float f0 = d0[16 + ub] + xp2.x,  f1 = d0[17 + ub] + xp2.y;
            float o0 = d0[24 + ub] + xp3.x,  o1 = d0[25 + ub] + xp3.y;
            c.x = c.x * sigm(f0 + 1.0f) + sigm(i0) * tanh_f(j0);
            c.y = c.y * sigm(f1 + 1.0f) + sigm(i1) * tanh_f(j1);
            hv.x = tanh_f(c.x) * sigm(o0);
            hv.y = tanh_f(c.y) * sigm(o1);
        }

        // ---- write split h (bf16 hi/lo) + fp32 output ----
        {
            __nv_bfloat16 h0h = __float2bfloat16(hv.x);
            __nv_bfloat16 h1h = __float2bfloat16(hv.y);
            __nv_bfloat16 h0l = __float2bfloat16(hv.x - __bfloat162float(h0h));
            __nv_bfloat16 h1l = __float2bfloat16(hv.y - __bfloat162float(h1h));
            unsigned phi = (unsigned)__bfloat16_as_ushort(h0h) |
                           ((unsigned)__bfloat16_as_ushort(h1h) << 16);
            unsigned plo = (unsigned)__bfloat16_as_ushort(h0l) |
                           ((unsigned)__bfloat16_as_ushort(h1l) << 16);
            __stcg(reinterpret_cast<unsigned*>(&g_hbf[p ^ 1][0][(b << 10) + ug]), phi);
            __stcg(reinterpret_cast<unsigned*>(&g_hbf[p ^ 1][1][(b << 10) + ug]), plo);
            *reinterpret_cast<float2*>(out + (size_t)b * (TT * UU) + (size_t)step * UU + ug) = hv;
        }

        gridbar(step + 1);
    }
}

// ---------------- launch ----------------
extern "C" void kernel_launch(void* const* d_in, const int* in_sizes, int n_in,
                              void* d_out, int out_size) {
    (void)in_sizes; (void)n_in; (void)out_size;
    const float* inputs = (const float*)d_in[0];
    const float* kern   = (const float*)d_in[1];
    const float* bias   = (const float*)d_in[2];
    float* out = (float*)d_out;

    cudaFuncSetAttribute(k_recur, cudaFuncAttributeMaxDynamicSharedMemorySize, SMEM_RECUR);
    cudaFuncSetAttribute(k_xproj_mma, cudaFuncAttributeMaxDynamicSharedMemorySize, XSMEM);

    k_init<<<512, 256>>>();                                // launch 1
    k_split_x<<<MM * DD / (256 * 8), 256>>>(inputs);       // launch 2
    {
        dim3 gw(GG / 32, DD / 32);
        k_split_w<<<gw, 256>>>(kern);                      // launch 3 (Wx = kern rows [0,512))
    }
    k_dummy<<<1, 32>>>();                                  // launch 4 (ncu alignment)
    {
        dim3 g1(GG / 64, MM / 128);                        // (64, 512)
        k_xproj_mma<<<g1, 256, XSMEM>>>(bias);             // launch 5
    }
    k_recur<<<NCTA, 256, SMEM_RECUR>>>(kern, out);         // launch 6 <- ncu -s 5 profiles this
}

// round 16
// speedup vs baseline: 3.3835x; 1.0122x over previous
#include <cuda_runtime.h>
#include <cuda_bf16.h>
#include <math.h>
#include <stdint.h>

// Problem constants
#define BB 64
#define TT 1024
#define DD 512
#define UU 1024
#define GG 4096           // 4*U
#define MM 65536          // B*T
#define NCTA 128          // persistent recurrent grid

// ---------------- scratch (static __device__, no allocs) ----------------
__device__ float g_xproj[(size_t)MM * GG];          // 1 GiB: x@Wx + bias, layout [t][b][g]
__device__ __nv_bfloat16 g_xhi[(size_t)MM * DD];    // 64MB X hi split [m][k]
__device__ __nv_bfloat16 g_xlo[(size_t)MM * DD];    // 64MB X lo split
__device__ __nv_bfloat16 g_whi[(size_t)GG * DD];    // 4MB Wx^T hi [n][k]
__device__ __nv_bfloat16 g_wlo[(size_t)GG * DD];    // 4MB Wx^T lo
__device__ __nv_bfloat16 g_hbf[2][2][BB * UU];      // [buf][hi/lo][b*1024+k]
__device__ unsigned g_count;
__device__ unsigned g_release;

// ---------------- k_recur smem layout (bytes) ----------------
// W slices padded to 1032 bf16/row (2064B): 2064/16=129 ≡ 1 (mod 8) -> ldmatrix conflict-free
#define WPAD 1032
#define OFF_WHI 0
#define OFF_WLO (32 * WPAD * 2)                   // 66048
#define OFF_A   (OFF_WLO + 32 * WPAD * 2)         // 132096
#define APAD 72                                    // A row = 144B; 144/16=9 ≡ 1 (mod 8)
#define ASPLIT (64 * APAD * 2)                     // 9216 B per split
#define ABUF   (2 * ASPLIT)                        // 18432 B per buffer (hi+lo); 3 buffers
#define OFF_D  (OFF_A + 3 * ABUF)                  // 187392
#define SMEM_RECUR (OFF_D + 64 * 33 * 4)           // 195840 B

// ---------------- k_xproj_mma smem layout ----------------
#define XAPAD 40                                   // 80B row stride; bank-conflict-free for ldmatrix
#define XA_SPLIT (128 * XAPAD * 2)                 // 10240
#define XA_BUF (2 * XA_SPLIT)                      // 20480 (hi+lo)
#define XB_SPLIT (64 * XAPAD * 2)                  // 5120
#define XB_BUF (2 * XB_SPLIT)                      // 10240
#define XOFF_A 0
#define XOFF_B (3 * XA_BUF)                        // 61440
#define XSMEM (XOFF_B + 3 * XB_BUF)                // 92160

// ---------------- PTX helpers (plain sm_80+ PTX, valid on sm_103) ----------------
__device__ __forceinline__ uint32_t smem_to_u32(const void* p) {
    uint32_t a;
    asm("{ .reg .u64 t; cvta.to.shared.u64 t, %1; cvt.u32.u64 %0, t; }" : "=r"(a) : "l"(p));
    return a;
}

__device__ __forceinline__ void cp_async16(uint32_t saddr, const void* gaddr) {
    asm volatile("cp.async.cg.shared.global [%0], [%1], 16;" :: "r"(saddr), "l"(gaddr));
}
#define CP_COMMIT() asm volatile("cp.async.commit_group;" ::: "memory")
#define CP_WAIT(n)  asm volatile("cp.async.wait_group %0;" :: "n"(n) : "memory")

__device__ __forceinline__ void ldmatrix_x4(uint32_t* r, uint32_t addr) {
    asm volatile("ldmatrix.sync.aligned.m8n8.x4.shared.b16 {%0,%1,%2,%3}, [%4];"
                 : "=r"(r[0]), "=r"(r[1]), "=r"(r[2]), "=r"(r[3]) : "r"(addr));
}

__device__ __forceinline__ void mma_bf16(float* d, const uint32_t* a, uint32_t b0, uint32_t b1) {
    asm volatile(
        "mma.sync.aligned.m16n8k16.row.col.f32.bf16.bf16.f32 "
        "{%0,%1,%2,%3}, {%4,%5,%6,%7}, {%8,%9}, {%0,%1,%2,%3};"
        : "+f"(d[0]), "+f"(d[1]), "+f"(d[2]), "+f"(d[3])
        : "r"(a[0]), "r"(a[1]), "r"(a[2]), "r"(a[3]), "r"(b0), "r"(b1));
}

// ---------------- misc math ----------------
__device__ __forceinline__ float sigm(float x) { return 1.0f / (1.0f + __expf(-x)); }
__device__ __forceinline__ float tanh_f(float x) {
    return 1.0f - 2.0f / (__expf(2.0f * x) + 1.0f);
}

// ---------------- grid barrier (monotonic release, L2-coherent) ----------------
__device__ __forceinline__ void gridbar(unsigned s) {
    __syncthreads();
    if (threadIdx.x == 0) {
        __threadfence();
        unsigned prev = atomicAdd(&g_count, 1u);
        if (prev + 1u == (unsigned)NCTA * s) {
            atomicExch(&g_release, s);
        } else {
            volatile unsigned* rel = &g_release;
            while (*rel < s) { }
            __threadfence();
        }
    }
    __syncthreads();
}

// ---------------- init (runs every replay) ----------------
__global__ void k_init() {
    int i = blockIdx.x * blockDim.x + threadIdx.x;
    if (i < 131072) ((unsigned*)g_hbf)[i] = 0u;   // 512KB of bf16 zeros
    if (i == 0) { g_count = 0u; g_release = 0u; }
}

// ---------------- merged prepass: split X and transpose+split Wx ----------------
// blocks [0, 16384): X fp32 -> bf16 hi/lo, [m][k]
// blocks [16384, 18432): Wx[k][n] -> [n][k] bf16 hi/lo (32x32 smem transpose tiles)
__global__ __launch_bounds__(256) void k_split(const float* __restrict__ X,
                                               const float* __restrict__ Wx) {
    __shared__ float ts[32][33];
    if (blockIdx.x < 16384) {
        int idx = blockIdx.x * 256 + threadIdx.x;
        const float* src = X + (size_t)idx * 8;
        float4 v0 = *reinterpret_cast<const float4*>(src);
        float4 v1 = *reinterpret_cast<const float4*>(src + 4);
        float f[8] = {v0.x, v0.y, v0.z, v0.w, v1.x, v1.y, v1.z, v1.w};
        unsigned hi[4], lo[4];
#pragma unroll
        for (int i = 0; i < 4; i++) {
            __nv_bfloat16 h0 = __float2bfloat16(f[2 * i]);
            __nv_bfloat16 h1 = __float2bfloat16(f[2 * i + 1]);
            __nv_bfloat16 l0 = __float2bfloat16(f[2 * i]     - __bfloat162float(h0));
            __nv_bfloat16 l1 = __float2bfloat16(f[2 * i + 1] - __bfloat162float(h1));
            hi[i] = (unsigned)__bfloat16_as_ushort(h0) | ((unsigned)__bfloat16_as_ushort(h1) << 16);
            lo[i] = (unsigned)__bfloat16_as_ushort(l0) | ((unsigned)__bfloat16_as_ushort(l1) << 16);
        }
        *reinterpret_cast<uint4*>(g_xhi + (size_t)idx * 8) = make_uint4(hi[0], hi[1], hi[2], hi[3]);
        *reinterpret_cast<uint4*>(g_xlo + (size_t)idx * 8) = make_uint4(lo[0], lo[1], lo[2], lo[3]);
    } else {
        int wtile = blockIdx.x - 16384;              // 0..2047
        const int n0 = (wtile & 127) * 32;           // 128 n-tiles
        const int k0 = (wtile >> 7) * 32;            // 16 k-tiles
        const int c = threadIdx.x & 31;
        const int rw = threadIdx.x >> 5;
#pragma unroll
        for (int rr = 0; rr < 4; rr++) {
            int r = rw + rr * 8;
            ts[r][c] = Wx[(size_t)(k0 + r) * GG + n0 + c];
        }
        __syncthreads();
#pragma unroll
        for (int rr = 0; rr < 4; rr++) {
            int r = rw + rr * 8;
            float v = ts[c][r];
            __nv_bfloat16 h = __float2bfloat16(v);
            __nv_bfloat16 l = __float2bfloat16(v - __bfloat162float(h));
            g_whi[(size_t)(n0 + r) * DD + k0 + c] = h;
            g_wlo[(size_t)(n0 + r) * DD + k0 + c] = l;
        }
    }
}

// ---------------- phase 1: x_proj via mma.sync (hi/lo 3-pass) ----------------
__global__ __launch_bounds__(256) void k_xproj_mma(const float* __restrict__ bias) {
    extern __shared__ char sm[];
    const uint32_t smb = smem_to_u32(sm);
    const int tid = threadIdx.x;
    const int wid = tid >> 5;
    const int lid = tid & 31;
    const int m0 = blockIdx.y * 128;
    const int n0 = blockIdx.x * 64;
    const int wm = wid >> 1;
    const int wn = wid & 1;

    const int sa_split = tid >> 7;
    const int sa_row   = tid & 127;
    const __nv_bfloat16* xsrc = (sa_split ? g_xlo : g_xhi) + (size_t)(m0 + sa_row) * DD;
    const uint32_t sa_dst = smb + XOFF_A + (uint32_t)(sa_split * XA_SPLIT + sa_row * (XAPAD * 2));
    const int sb_split = (tid >> 6) & 1;
    const int sb_row   = tid & 63;
    const __nv_bfloat16* wsrc = (sb_split ? g_wlo : g_whi) + (size_t)(n0 + sb_row) * DD;
    const uint32_t sb_dst = smb + XOFF_B + (uint32_t)(sb_split * XB_SPLIT + sb_row * (XAPAD * 2));

    const uint32_t a_lane0 = smb + XOFF_A +
        (uint32_t)((wm * 32 + (lid & 15)) * (XAPAD * 2) + ((lid >> 4) * 8) * 2);
    const uint32_t a_lane1 = a_lane0 + (uint32_t)(16 * (XAPAD * 2));
    const uint32_t b_lane0 = smb + XOFF_B +
        (uint32_t)((wn * 32 + (lid & 7) + ((lid >> 4) << 3)) * (XAPAD * 2) + (((lid >> 3) & 1) * 8) * 2);
    const uint32_t b_lane1 = b_lane0 + (uint32_t)(16 * (XAPAD * 2));

    float acc[2][4][4];
#pragma unroll
    for (int a = 0; a < 2; a++)
#pragma unroll
        for (int j = 0; j < 4; j++)
#pragma unroll
            for (int e = 0; e < 4; e++) acc[a][j][e] = 0.f;

    auto stage = [&](int ck) {
        const uint32_t da = sa_dst + (uint32_t)((ck % 3) * XA_BUF);
        const __nv_bfloat16* s = xsrc + ck * 32;
#pragma unroll
        for (int c4 = 0; c4 < 4; c4++) cp_async16(da + c4 * 16, s + c4 * 8);
        if (tid < 128) {
            const uint32_t db = sb_dst + (uint32_t)((ck % 3) * XB_BUF);
            const __nv_bfloat16* sb = wsrc + ck * 32;
#pragma unroll
            for (int c4 = 0; c4 < 4; c4++) cp_async16(db + c4 * 16, sb + c4 * 8);
        }
        CP_COMMIT();
    };

    stage(0);
    stage(1);

#pragma unroll 1
    for (int kc = 0; kc < 16; kc++) {
        if (kc < 15) { CP_WAIT(1); } else { CP_WAIT(0); }
        __syncthreads();
        if (kc < 14) stage(kc + 2);

        const uint32_t aoff = (uint32_t)((kc % 3) * XA_BUF);
        const uint32_t boff = (uint32_t)((kc % 3) * XB_BUF);
#pragma unroll
        for (int ks = 0; ks < 2; ks++) {
            uint32_t ah0[4], ah1[4], al0[4], al1[4];
            uint32_t bh0[4], bh1[4], bl0[4], bl1[4];
            ldmatrix_x4(ah0, a_lane0 + aoff + ks * 32);
            ldmatrix_x4(ah1, a_lane1 + aoff + ks * 32);
            ldmatrix_x4(al0, a_lane0 + aoff + XA_SPLIT + ks * 32);
            ldmatrix_x4(al1, a_lane1 + aoff + XA_SPLIT + ks * 32);
            ldmatrix_x4(bh0, b_lane0 + boff + ks * 32);
            ldmatrix_x4(bh1, b_lane1 + boff + ks * 32);
            ldmatrix_x4(bl0, b_lane0 + boff + XB_SPLIT + ks * 32);
            ldmatrix_x4(bl1, b_lane1 + boff + XB_SPLIT + ks * 32);
            mma_bf16(acc[0][0], ah0, bh0[0], bh0[1]); mma_bf16(acc[0][1], ah0, bh0[2], bh0[3]);
            mma_bf16(acc[0][2], ah0, bh1[0], bh1[1]); mma_bf16(acc[0][3], ah0, bh1[2], bh1[3]);
            mma_bf16(acc[1][0], ah1, bh0[0], bh0[1]); mma_bf16(acc[1][1], ah1, bh0[2], bh0[3]);
            mma_bf16(acc[1][2], ah1, bh1[0], bh1[1]); mma_bf16(acc[1][3], ah1, bh1[2], bh1[3]);
            mma_bf16(acc[0][0], ah0, bl0[0], bl0[1]); mma_bf16(acc[0][1], ah0, bl0[2], bl0[3]);
            mma_bf16(acc[0][2], ah0, bl1[0], bl1[1]); mma_bf16(acc[0][3], ah0, bl1[2], bl1[3]);
            mma_bf16(acc[1][0], ah1, bl0[0], bl0[1]); mma_bf16(acc[1][1], ah1, bl0[2], bl0[3]);
            mma_bf16(acc[1][2], ah1, bl1[0], bl1[1]); mma_bf16(acc[1][3], ah1, bl1[2], bl1[3]);
            mma_bf16(acc[0][0], al0, bh0[0], bh0[1]); mma_bf16(acc[0][1], al0, bh0[2], bh0[3]);
            mma_bf16(acc[0][2], al0, bh1[0], bh1[1]); mma_bf16(acc[0][3], al0, bh1[2], bh1[3]);
            mma_bf16(acc[1][0], al1, bh0[0], bh0[1]); mma_bf16(acc[1][1], al1, bh0[2], bh0[3]);
            mma_bf16(acc[1][2], al1, bh1[0], bh1[1]); mma_bf16(acc[1][3], al1, bh1[2], bh1[3]);
        }
    }

    const int er = lid >> 2;
    const int ec = (lid & 3) * 2;
#pragma unroll
    for (int mt = 0; mt < 2; mt++) {
        int mr = m0 + wm * 32 + mt * 16 + er;
#pragma unroll
        for (int j = 0; j < 4; j++) {
            int n = n0 + wn * 32 + j * 8 + ec;
            float2 bv = *reinterpret_cast<const float2*>(bias + n);
            int b0i = mr >> 10, t0i = mr & 1023;
            int b1i = (mr + 8) >> 10, t1i = (mr + 8) & 1023;
            float2 o0 = make_float2(acc[mt][j][0] + bv.x, acc[mt][j][1] + bv.y);
            float2 o1 = make_float2(acc[mt][j][2] + bv.x, acc[mt][j][3] + bv.y);
            *reinterpret_cast<float2*>(g_xproj + ((size_t)t0i * BB + b0i) * GG + n) = o0;
            *reinterpret_cast<float2*>(g_xproj + ((size_t)t1i * BB + b1i) * GG + n) = o1;
        }
    }
}

// ---------------- phase 2: persistent mma.sync recurrence ----------------
// 128 CTAs x 256 threads (8 warps). CTA owns 8 units = 32 gate-cols, M=64 batch, K=1024.
// hi/lo bf16 split; 3 mma passes; SIX independent accumulator chains per warp
// (hh/hl/lh x 2 n-tiles) to avoid dependent-HMMA stalls; summed after the k-loop.
// W resident in smem. h staged per 64-k chunk, 3-stage cp.async pipeline, 1 sync/chunk.
__global__ __launch_bounds__(256) void k_recur(const float* __restrict__ W,
                                               float* __restrict__ out) {
    extern __shared__ char sm[];
    const uint32_t smb = smem_to_u32(sm);
    const int tid = threadIdx.x;
    const int wid = tid >> 5;
    const int lid = tid & 31;
    const int cta = blockIdx.x;
    const float* Wh = W + (size_t)DD * GG;   // recurrent weights rows [512,1536)

    // ---- load W hi/lo split into smem (once): whsm[n][k], n = gate*8 + uo ----
    {
        __nv_bfloat16* whi = reinterpret_cast<__nv_bfloat16*>(sm + OFF_WHI);
        __nv_bfloat16* wlo = reinterpret_cast<__nv_bfloat16*>(sm + OFF_WLO);
        for (int i = tid; i < 32 * 1024; i += 256) {
            int k = i & 1023;
            int n = i >> 10;
            int col = (n >> 3) * UU + cta * 8 + (n & 7);
            float w = Wh[(size_t)k * GG + col];
            __nv_bfloat16 hi = __float2bfloat16(w);
            __nv_bfloat16 lo = __float2bfloat16(w - __bfloat162float(hi));
            whi[n * WPAD + k] = hi;
            wlo[n * WPAD + k] = lo;
        }
    }
    __syncthreads();

    const int wm = wid >> 1;
    const int wn = wid & 1;

    const int a_row  = wm * 16 + (lid & 15);
    const int a_koff = (lid >> 4) * 8;
    const uint32_t a_lane = smb + OFF_A + (uint32_t)(a_row * (APAD * 2) + a_koff * 2);
    const int b_row  = wn * 16 + (lid & 7) + ((lid >> 4) << 3);
    const int b_koff = ((lid >> 3) & 1) * 8;
    const uint32_t bhi_lane = smb + OFF_WHI + (uint32_t)(b_row * (WPAD * 2) + b_koff * 2);
    const uint32_t blo_lane = smb + OFF_WLO + (uint32_t)(b_row * (WPAD * 2) + b_koff * 2);

    const int s_split = tid >> 7;
    const int s_row   = (tid & 127) >> 1;
    const int s_half  = (tid & 1) * 32;
    const uint32_t s_sm = smb + OFF_A + (uint32_t)(s_split * ASPLIT +
                           s_row * (APAD * 2) + s_half * 2);

    const int b  = tid >> 2;
    const int q  = tid & 3;
    const int ub = q * 2;
    const int ug = cta * 8 + ub;
    float* Dsm = reinterpret_cast<float*>(sm + OFF_D);    // [64][33]

    float2 c = make_float2(0.f, 0.f);

    for (int step = 0; step < TT; ++step) {
        const int p = step & 1;

        const float* xrow = g_xproj + (size_t)step * (BB * GG) + (size_t)b * GG;
        float2 xp0 = __ldcg(reinterpret_cast<const float2*>(xrow + 0 * UU + ug));
        float2 xp1 = __ldcg(reinterpret_cast<const float2*>(xrow + 1 * UU + ug));
        float2 xp2 = __ldcg(reinterpret_cast<const float2*>(xrow + 2 * UU + ug));
        float2 xp3 = __ldcg(reinterpret_cast<const float2*>(xrow + 3 * UU + ug));

        const __nv_bfloat16* hsrc = g_hbf[p][s_split] + (s_row << 10) + s_half;

        // SIX independent accumulator chains
        float ahh0[4] = {0.f, 0.f, 0.f, 0.f}, ahh1[4] = {0.f, 0.f, 0.f, 0.f};
        float ahl0[4] = {0.f, 0.f, 0.f, 0.f}, ahl1[4] = {0.f, 0.f, 0.f, 0.f};
        float alh0[4] = {0.f, 0.f, 0.f, 0.f}, alh1[4] = {0.f, 0.f, 0.f, 0.f};

        // 3-stage pipeline prologue
        {
#pragma unroll
            for (int c4 = 0; c4 < 4; c4++) cp_async16(s_sm + c4 * 16, hsrc + c4 * 8);
            CP_COMMIT();
            const uint32_t d1 = s_sm + ABUF;
#pragma unroll
            for (int c4 = 0; c4 < 4; c4++) cp_async16(d1 + c4 * 16, hsrc + 64 + c4 * 8);
            CP_COMMIT();
        }

#pragma unroll 1
        for (int kt = 0; kt < 16; kt++) {
            if (kt < 15) { CP_WAIT(1); } else { CP_WAIT(0); }
            __syncthreads();
            if (kt < 14) {
                const uint32_t dst = s_sm + (uint32_t)(((kt + 2) % 3) * ABUF);
                const __nv_bfloat16* src = hsrc + (kt + 2) * 64;
#pragma unroll
                for (int c4 = 0; c4 < 4; c4++) cp_async16(dst + c4 * 16, src + c4 * 8);
                CP_COMMIT();
            }

            const uint32_t abase = a_lane + (uint32_t)((kt % 3) * ABUF);
            const uint32_t bkoff = (uint32_t)(kt * 128);
#pragma unroll
            for (int ks = 0; ks < 4; ks++) {
                uint32_t ah[4], al[4], bh[4], bl[4];
                ldmatrix_x4(ah, abase + ks * 32);
                ldmatrix_x4(al, abase + ASPLIT + ks * 32);
                ldmatrix_x4(bh, bhi_lane + bkoff + ks * 32);
                ldmatrix_x4(bl, blo_lane + bkoff + ks * 32);
                mma_bf16(ahh0, ah, bh[0], bh[1]);
                mma_bf16(ahh1, ah, bh[2], bh[3]);
                mma_bf16(ahl0, ah, bl[0], bl[1]);
                mma_bf16(ahl1, ah, bl[2], bl[3]);
                mma_bf16(alh0, al, bh[0], bh[1]);
                mma_bf16(alh1, al, bh[2], bh[3]);
            }
        }

        // ---- combine chains + dump to smem gates buffer ----
        {
            int r0 = wm * 16 + (lid >> 2);
            int c0 = wn * 16 + (lid & 3) * 2;
            float v00 = ahh0[0] + ahl0[0] + alh0[0];
            float v01 = ahh0[1] + ahl0[1] + alh0[1];
            float v02 = ahh0[2] + ahl0[2] + alh0[2];
            float v03 = ahh0[3] + ahl0[3] + alh0[3];
            float v10 = ahh1[0] + ahl1[0] + alh1[0];
            float v11 = ahh1[1] + ahl1[1] + alh1[1];
            float v12 = ahh1[2] + ahl1[2] + alh1[2];
            float v13 = ahh1[3] + ahl1[3] + alh1[3];
            Dsm[r0 * 33 + c0]           = v00;
            Dsm[r0 * 33 + c0 + 1]       = v01;
            Dsm[(r0 + 8) * 33 + c0]     = v02;
            Dsm[(r0 + 8) * 33 + c0 + 1] = v03;
            Dsm[r0 * 33 + c0 + 8]           = v10;
            Dsm[r0 * 33 + c0 + 9]           = v11;
            Dsm[(r0 + 8) * 33 + c0 + 8]     = v12;
            Dsm[(r0 + 8) * 33 + c0 + 9]     = v13;
        }
        __syncthreads();

        // ---- register-local cell update ----
        float2 hv;
        {
            const float* d0 = Dsm + b * 33;
            float i0 = d0[ub]      + xp0.x,  i1 = d0[ub + 1]  + xp0.y;
            float j0 = d0[8 + ub]  + xp1.x,  j1 = d0[9 + ub]  + xp1.y;
            float f0 = d0[16 + ub] + xp2.x,  f1 = d0[17 + ub] + xp2.y;
            float o0 = d0[24 + ub] + xp3.x,  o1 = d0[25 + ub] + xp3.y;
            c.x = c.x * sigm(f0 + 1.0f) + sigm(i0) * tanh_f(j0);
            c.y = c.y * sigm(f1 + 1.0f) + sigm(i1) * tanh_f(j1);
            hv.x = tanh_f(c.x) * sigm(o0);
            hv.y = tanh_f(c.y) * sigm(o1);
        }

        // ---- write split h (bf16 hi/lo) + fp32 output ----
        {
            __nv_bfloat16 h0h = __float2bfloat16(hv.x);
            __nv_bfloat16 h1h = __float2bfloat16(hv.y);
            __nv_bfloat16 h0l = __float2bfloat16(hv.x - __bfloat162float(h0h));
            __nv_bfloat16 h1l = __float2bfloat16(hv.y - __bfloat162float(h1h));
            unsigned phi = (unsigned)__bfloat16_as_ushort(h0h) |
                           ((unsigned)__bfloat16_as_ushort(h1h) << 16);
            unsigned plo = (unsigned)__bfloat16_as_ushort(h0l) |
                           ((unsigned)__bfloat16_as_ushort(h1l) << 16);
            __stcg(reinterpret_cast<unsigned*>(&g_hbf[p ^ 1][0][(b << 10) + ug]), phi);
            __stcg(reinterpret_cast<unsigned*>(&g_hbf[p ^ 1][1][(b << 10) + ug]), plo);
            *reinterpret_cast<float2*>(out + (size_t)b * (TT * UU) + (size_t)step * UU + ug) = hv;
        }

        gridbar(step + 1);
    }
}

// ---------------- launch ----------------
extern "C" void kernel_launch(void* const* d_in, const int* in_sizes, int n_in,
                              void* d_out, int out_size) {
    (void)in_sizes; (void)n_in; (void)out_size;
    const float* inputs = (const float*)d_in[0];
    const float* kern   = (const float*)d_in[1];
    const float* bias   = (const float*)d_in[2];
    float* out = (float*)d_out;

    cudaFuncSetAttribute(k_recur, cudaFuncAttributeMaxDynamicSharedMemorySize, SMEM_RECUR);
    cudaFuncSetAttribute(k_xproj_mma, cudaFuncAttributeMaxDynamicSharedMemorySize, XSMEM);

    k_init<<<512, 256>>>();                                // launch 1
    k_split<<<16384 + 2048, 256>>>(inputs, kern);          // launch 2 (X + Wx prepass merged)
    {
        dim3 g1(GG / 64, MM / 128);                        // (64, 512)
        k_xproj_mma<<<g1, 256, XSMEM>>>(bias);             // launch 3
    }
    k_recur<<<NCTA, 256, SMEM_RECUR>>>(kern, out);         // launch 4 <- ncu captures 4th launch
}

// round 17
// speedup vs baseline: 3.6663x; 1.0836x over previous
#include <cuda_runtime.h>
#include <cuda_bf16.h>
#include <math.h>
#include <stdint.h>

// Problem constants
#define BB 64
#define TT 1024
#define DD 512
#define UU 1024
#define GG 4096           // 4*U
#define MM 65536          // B*T
#define NCTA 128          // persistent recurrent grid

// ---------------- scratch (static __device__, no allocs) ----------------
__device__ float g_xproj[(size_t)MM * GG];          // 1 GiB: x@Wx + bias, layout [t][b][g]
__device__ __nv_bfloat16 g_xhi[(size_t)MM * DD];    // 64MB X hi split [m][k]
__device__ __nv_bfloat16 g_xlo[(size_t)MM * DD];    // 64MB X lo split
__device__ __nv_bfloat16 g_whi[(size_t)GG * DD];    // 4MB Wx^T hi [n][k]
__device__ __nv_bfloat16 g_wlo[(size_t)GG * DD];    // 4MB Wx^T lo
__device__ __nv_bfloat16 g_hbf[2][2][BB * UU];      // [buf][hi/lo][b*1024+k]
__device__ unsigned g_count;
__device__ unsigned g_release;

// ---------------- k_recur smem layout (bytes) ----------------
// W slices padded to 1032 bf16/row (2064B) -> ldmatrix conflict-free
#define WPAD 1032
#define OFF_WHI 0
#define OFF_WLO (32 * WPAD * 2)                   // 66048
#define OFF_A   (OFF_WLO + 32 * WPAD * 2)         // 132096
#define APAD 72                                    // A row = 144B
#define ASPLIT (64 * APAD * 2)                     // 9216 B per split
#define ABUF   (2 * ASPLIT)                        // 18432 B per buffer (hi+lo); 4 buffers
#define SMEM_RECUR (OFF_A + 4 * ABUF)              // 205824 B

// ---------------- k_xproj_mma smem layout ----------------
#define XAPAD 40
#define XA_SPLIT (128 * XAPAD * 2)                 // 10240
#define XA_BUF (2 * XA_SPLIT)                      // 20480 (hi+lo)
#define XB_SPLIT (64 * XAPAD * 2)                  // 5120
#define XB_BUF (2 * XB_SPLIT)                      // 10240
#define XOFF_A 0
#define XOFF_B (3 * XA_BUF)                        // 61440
#define XSMEM (XOFF_B + 3 * XB_BUF)                // 92160

// ---------------- PTX helpers (plain sm_80+ PTX, valid on sm_103) ----------------
__device__ __forceinline__ uint32_t smem_to_u32(const void* p) {
    uint32_t a;
    asm("{ .reg .u64 t; cvta.to.shared.u64 t, %1; cvt.u32.u64 %0, t; }" : "=r"(a) : "l"(p));
    return a;
}

__device__ __forceinline__ void cp_async16(uint32_t saddr, const void* gaddr) {
    asm volatile("cp.async.cg.shared.global [%0], [%1], 16;" :: "r"(saddr), "l"(gaddr));
}
#define CP_COMMIT() asm volatile("cp.async.commit_group;" ::: "memory")
#define CP_WAIT(n)  asm volatile("cp.async.wait_group %0;" :: "n"(n) : "memory")

#define PAIR_BAR(id) asm volatile("bar.sync %0, 64;" :: "r"(id) : "memory")

__device__ __forceinline__ void ldmatrix_x4(uint32_t* r, uint32_t addr) {
    asm volatile("ldmatrix.sync.aligned.m8n8.x4.shared.b16 {%0,%1,%2,%3}, [%4];"
                 : "=r"(r[0]), "=r"(r[1]), "=r"(r[2]), "=r"(r[3]) : "r"(addr));
}

__device__ __forceinline__ void mma_bf16(float* d, const uint32_t* a, uint32_t b0, uint32_t b1) {
    asm volatile(
        "mma.sync.aligned.m16n8k16.row.col.f32.bf16.bf16.f32 "
        "{%0,%1,%2,%3}, {%4,%5,%6,%7}, {%8,%9}, {%0,%1,%2,%3};"
        : "+f"(d[0]), "+f"(d[1]), "+f"(d[2]), "+f"(d[3])
        : "r"(a[0]), "r"(a[1]), "r"(a[2]), "r"(a[3]), "r"(b0), "r"(b1));
}

__device__ __forceinline__ void st_u16_cg(__nv_bfloat16* p, __nv_bfloat16 v) {
    unsigned short u = __bfloat16_as_ushort(v);
    asm volatile("st.global.cg.u16 [%0], %1;" :: "l"(p), "h"(u) : "memory");
}

// ---------------- misc math ----------------
__device__ __forceinline__ float sigm(float x) { return 1.0f / (1.0f + __expf(-x)); }
__device__ __forceinline__ float tanh_f(float x) {
    return 1.0f - 2.0f / (__expf(2.0f * x) + 1.0f);
}

// ---------------- grid barrier (monotonic release, L2-coherent) ----------------
__device__ __forceinline__ void gridbar(unsigned s) {
    __syncthreads();
    if (threadIdx.x == 0) {
        __threadfence();
        unsigned prev = atomicAdd(&g_count, 1u);
        if (prev + 1u == (unsigned)NCTA * s) {
            atomicExch(&g_release, s);
        } else {
            volatile unsigned* rel = &g_release;
            while (*rel < s) { }
            __threadfence();
        }
    }
    __syncthreads();
}

// ---------------- init (runs every replay) ----------------
__global__ void k_init() {
    int i = blockIdx.x * blockDim.x + threadIdx.x;
    if (i < 131072) ((unsigned*)g_hbf)[i] = 0u;   // 512KB of bf16 zeros
    if (i == 0) { g_count = 0u; g_release = 0u; }
}

// ---------------- merged prepass: split X and transpose+split Wx ----------------
__global__ __launch_bounds__(256) void k_split(const float* __restrict__ X,
                                               const float* __restrict__ Wx) {
    __shared__ float ts[32][33];
    if (blockIdx.x < 16384) {
        int idx = blockIdx.x * 256 + threadIdx.x;
        const float* src = X + (size_t)idx * 8;
        float4 v0 = *reinterpret_cast<const float4*>(src);
        float4 v1 = *reinterpret_cast<const float4*>(src + 4);
        float f[8] = {v0.x, v0.y, v0.z, v0.w, v1.x, v1.y, v1.z, v1.w};
        unsigned hi[4], lo[4];
#pragma unroll
        for (int i = 0; i < 4; i++) {
            __nv_bfloat16 h0 = __float2bfloat16(f[2 * i]);
            __nv_bfloat16 h1 = __float2bfloat16(f[2 * i + 1]);
            __nv_bfloat16 l0 = __float2bfloat16(f[2 * i]     - __bfloat162float(h0));
            __nv_bfloat16 l1 = __float2bfloat16(f[2 * i + 1] - __bfloat162float(h1));
            hi[i] = (unsigned)__bfloat16_as_ushort(h0) | ((unsigned)__bfloat16_as_ushort(h1) << 16);
            lo[i] = (unsigned)__bfloat16_as_ushort(l0) | ((unsigned)__bfloat16_as_ushort(l1) << 16);
        }
        *reinterpret_cast<uint4*>(g_xhi + (size_t)idx * 8) = make_uint4(hi[0], hi[1], hi[2], hi[3]);
        *reinterpret_cast<uint4*>(g_xlo + (size_t)idx * 8) = make_uint4(lo[0], lo[1], lo[2], lo[3]);
    } else {
        int wtile = blockIdx.x - 16384;              // 0..2047
        const int n0 = (wtile & 127) * 32;
        const int k0 = (wtile >> 7) * 32;
        const int c = threadIdx.x & 31;
        const int rw = threadIdx.x >> 5;
#pragma unroll
        for (int rr = 0; rr < 4; rr++) {
            int r = rw + rr * 8;
            ts[r][c] = Wx[(size_t)(k0 + r) * GG + n0 + c];
        }
        __syncthreads();
#pragma unroll
        for (int rr = 0; rr < 4; rr++) {
            int r = rw + rr * 8;
            float v = ts[c][r];
            __nv_bfloat16 h = __float2bfloat16(v);
            __nv_bfloat16 l = __float2bfloat16(v - __bfloat162float(h));
            g_whi[(size_t)(n0 + r) * DD + k0 + c] = h;
            g_wlo[(size_t)(n0 + r) * DD + k0 + c] = l;
        }
    }
}

// ---------------- phase 1: x_proj via mma.sync (hi/lo 3-pass) ----------------
__global__ __launch_bounds__(256) void k_xproj_mma(const float* __restrict__ bias) {
    extern __shared__ char sm[];
    const uint32_t smb = smem_to_u32(sm);
    const int tid = threadIdx.x;
    const int wid = tid >> 5;
    const int lid = tid & 31;
    const int m0 = blockIdx.y * 128;
    const int n0 = blockIdx.x * 64;
    const int wm = wid >> 1;
    const int wn = wid & 1;

    const int sa_split = tid >> 7;
    const int sa_row   = tid & 127;
    const __nv_bfloat16* xsrc = (sa_split ? g_xlo : g_xhi) + (size_t)(m0 + sa_row) * DD;
    const uint32_t sa_dst = smb + XOFF_A + (uint32_t)(sa_split * XA_SPLIT + sa_row * (XAPAD * 2));
    const int sb_split = (tid >> 6) & 1;
    const int sb_row   = tid & 63;
    const __nv_bfloat16* wsrc = (sb_split ? g_wlo : g_whi) + (size_t)(n0 + sb_row) * DD;
    const uint32_t sb_dst = smb + XOFF_B + (uint32_t)(sb_split * XB_SPLIT + sb_row * (XAPAD * 2));

    const uint32_t a_lane0 = smb + XOFF_A +
        (uint32_t)((wm * 32 + (lid & 15)) * (XAPAD * 2) + ((lid >> 4) * 8) * 2);
    const uint32_t a_lane1 = a_lane0 + (uint32_t)(16 * (XAPAD * 2));
    const uint32_t b_lane0 = smb + XOFF_B +
        (uint32_t)((wn * 32 + (lid & 7) + ((lid >> 4) << 3)) * (XAPAD * 2) + (((lid >> 3) & 1) * 8) * 2);
    const uint32_t b_lane1 = b_lane0 + (uint32_t)(16 * (XAPAD * 2));

    float acc[2][4][4];
#pragma unroll
    for (int a = 0; a < 2; a++)
#pragma unroll
        for (int j = 0; j < 4; j++)
#pragma unroll
            for (int e = 0; e < 4; e++) acc[a][j][e] = 0.f;

    auto stage = [&](int ck) {
        const uint32_t da = sa_dst + (uint32_t)((ck % 3) * XA_BUF);
        const __nv_bfloat16* s = xsrc + ck * 32;
#pragma unroll
        for (int c4 = 0; c4 < 4; c4++) cp_async16(da + c4 * 16, s + c4 * 8);
        if (tid < 128) {
            const uint32_t db = sb_dst + (uint32_t)((ck % 3) * XB_BUF);
            const __nv_bfloat16* sb = wsrc + ck * 32;
#pragma unroll
            for (int c4 = 0; c4 < 4; c4++) cp_async16(db + c4 * 16, sb + c4 * 8);
        }
        CP_COMMIT();
    };

    stage(0);
    stage(1);

#pragma unroll 1
    for (int kc = 0; kc < 16; kc++) {
        if (kc < 15) { CP_WAIT(1); } else { CP_WAIT(0); }
        __syncthreads();
        if (kc < 14) stage(kc + 2);

        const uint32_t aoff = (uint32_t)((kc % 3) * XA_BUF);
        const uint32_t boff = (uint32_t)((kc % 3) * XB_BUF);
#pragma unroll
        for (int ks = 0; ks < 2; ks++) {
            uint32_t ah0[4], ah1[4], al0[4], al1[4];
            uint32_t bh0[4], bh1[4], bl0[4], bl1[4];
            ldmatrix_x4(ah0, a_lane0 + aoff + ks * 32);
            ldmatrix_x4(ah1, a_lane1 + aoff + ks * 32);
            ldmatrix_x4(al0, a_lane0 + aoff + XA_SPLIT + ks * 32);
            ldmatrix_x4(al1, a_lane1 + aoff + XA_SPLIT + ks * 32);
            ldmatrix_x4(bh0, b_lane0 + boff + ks * 32);
            ldmatrix_x4(bh1, b_lane1 + boff + ks * 32);
            ldmatrix_x4(bl0, b_lane0 + boff + XB_SPLIT + ks * 32);
            ldmatrix_x4(bl1, b_lane1 + boff + XB_SPLIT + ks * 32);
            mma_bf16(acc[0][0], ah0, bh0[0], bh0[1]); mma_bf16(acc[0][1], ah0, bh0[2], bh0[3]);
            mma_bf16(acc[0][2], ah0, bh1[0], bh1[1]); mma_bf16(acc[0][3], ah0, bh1[2], bh1[3]);
            mma_bf16(acc[1][0], ah1, bh0[0], bh0[1]); mma_bf16(acc[1][1], ah1, bh0[2], bh0[3]);
            mma_bf16(acc[1][2], ah1, bh1[0], bh1[1]); mma_bf16(acc[1][3], ah1, bh1[2], bh1[3]);
            mma_bf16(acc[0][0], ah0, bl0[0], bl0[1]); mma_bf16(acc[0][1], ah0, bl0[2], bl0[3]);
            mma_bf16(acc[0][2], ah0, bl1[0], bl1[1]); mma_bf16(acc[0][3], ah0, bl1[2], bl1[3]);
            mma_bf16(acc[1][0], ah1, bl0[0], bl0[1]); mma_bf16(acc[1][1], ah1, bl0[2], bl0[3]);
            mma_bf16(acc[1][2], ah1, bl1[0], bl1[1]); mma_bf16(acc[1][3], ah1, bl1[2], bl1[3]);
            mma_bf16(acc[0][0], al0, bh0[0], bh0[1]); mma_bf16(acc[0][1], al0, bh0[2], bh0[3]);
            mma_bf16(acc[0][2], al0, bh1[0], bh1[1]); mma_bf16(acc[0][3], al0, bh1[2], bh1[3]);
            mma_bf16(acc[1][0], al1, bh0[0], bh0[1]); mma_bf16(acc[1][1], al1, bh0[2], bh0[3]);
            mma_bf16(acc[1][2], al1, bh1[0], bh1[1]); mma_bf16(acc[1][3], al1, bh1[2], bh1[3]);
        }
    }

    const int er = lid >> 2;
    const int ec = (lid & 3) * 2;
#pragma unroll
    for (int mt = 0; mt < 2; mt++) {
        int mr = m0 + wm * 32 + mt * 16 + er;
#pragma unroll
        for (int j = 0; j < 4; j++) {
            int n = n0 + wn * 32 + j * 8 + ec;
            float2 bv = *reinterpret_cast<const float2*>(bias + n);
            int b0i = mr >> 10, t0i = mr & 1023;
            int b1i = (mr + 8) >> 10, t1i = (mr + 8) & 1023;
            float2 o0 = make_float2(acc[mt][j][0] + bv.x, acc[mt][j][1] + bv.y);
            float2 o1 = make_float2(acc[mt][j][2] + bv.x, acc[mt][j][3] + bv.y);
            *reinterpret_cast<float2*>(g_xproj + ((size_t)t0i * BB + b0i) * GG + n) = o0;
            *reinterpret_cast<float2*>(g_xproj + ((size_t)t1i * BB + b1i) * GG + n) = o1;
        }
    }
}

// ---------------- phase 2: persistent mma.sync recurrence ----------------
// 128 CTAs x 256 threads (8 warps). CTA owns 8 units = 32 gate-cols, M=64 batch, K=1024.
// W column map: n = unit*4 + gate  -> each warp owns all 4 gates of 4 units.
// Per-PAIR staging + named bar.sync (64 threads); 4-deep cp.async pipeline;
// shuffle epilogue (no smem exchange, no extra block syncs). One gridbar per step.
__global__ __launch_bounds__(256) void k_recur(const float* __restrict__ W,
                                               float* __restrict__ out) {
    extern __shared__ char sm[];
    const uint32_t smb = smem_to_u32(sm);
    const int tid = threadIdx.x;
    const int wid = tid >> 5;
    const int lid = tid & 31;
    const int cta = blockIdx.x;
    const float* Wh = W + (size_t)DD * GG;   // recurrent weights rows [512,1536)

    // ---- load W hi/lo split into smem (once): row n -> global col (n&3)*UU + cta*8 + (n>>2) ----
    {
        __nv_bfloat16* whi = reinterpret_cast<__nv_bfloat16*>(sm + OFF_WHI);
        __nv_bfloat16* wlo = reinterpret_cast<__nv_bfloat16*>(sm + OFF_WLO);
        for (int i = tid; i < 32 * 1024; i += 256) {
            int k = i & 1023;
            int n = i >> 10;
            int col = (n & 3) * UU + cta * 8 + (n >> 2);
            float w = Wh[(size_t)k * GG + col];
            __nv_bfloat16 hi = __float2bfloat16(w);
            __nv_bfloat16 lo = __float2bfloat16(w - __bfloat162float(hi));
            whi[n * WPAD + k] = hi;
            wlo[n * WPAD + k] = lo;
        }
    }
    __syncthreads();

    const int wm = wid >> 1;            // pair id 0..3 (m-tile of 16 batches)
    const int wn = wid & 1;             // n-half

    const int a_row  = wm * 16 + (lid & 15);
    const int a_koff = (lid >> 4) * 8;
    const uint32_t a_lane = smb + OFF_A + (uint32_t)(a_row * (APAD * 2) + a_koff * 2);
    const int b_row  = wn * 16 + (lid & 7) + ((lid >> 4) << 3);
    const int b_koff = ((lid >> 3) & 1) * 8;
    const uint32_t bhi_lane = smb + OFF_WHI + (uint32_t)(b_row * (WPAD * 2) + b_koff * 2);
    const uint32_t blo_lane = smb + OFF_WLO + (uint32_t)(b_row * (WPAD * 2) + b_koff * 2);

    // per-PAIR staging map: 64 threads cover rows [wm*16, wm*16+16) x hi/lo x 64k
    const int pt = tid & 63;
    const int s_split = pt >> 5;                 // 0:hi 1:lo
    const int s_rowin = (pt & 31) >> 1;          // 0..15
    const int s_half  = (pt & 1) * 32;           // k offset (bf16)
    const int s_grow  = wm * 16 + s_rowin;       // global batch row
    const uint32_t s_dst0 = smb + OFF_A + (uint32_t)(s_split * ASPLIT +
                            s_grow * (APAD * 2) + s_half * 2);
    const int bar_id = 1 + wm;

    // epilogue map: thread owns 2 cells (rows b0g, b0g+8) of one unit
    const int lane_odd = lid & 1;
    const int b0g = wm * 16 + (lid >> 2);
    const int myu = wn * 4 + ((lid & 3) >> 1) + (lane_odd ? 2 : 0);
    const int ug = cta * 8 + myu;

    __nv_bfloat16* hb_hi[2] = {g_hbf[0][0], g_hbf[1][0]};
    __nv_bfloat16* hb_lo[2] = {g_hbf[0][1], g_hbf[1][1]};

    float2 c = make_float2(0.f, 0.f);

    for (int step = 0; step < TT; ++step) {
        const int p = step & 1;

        // prefetch xproj gates for this thread's 2 cells (hidden under GEMM)
        const float* xb = g_xproj + (size_t)step * (BB * GG);
        float xpa[4], xpb[4];
#pragma unroll
        for (int g = 0; g < 4; g++) {
            xpa[g] = __ldcg(xb + (size_t)b0g * GG + g * UU + ug);
            xpb[g] = __ldcg(xb + (size_t)(b0g + 8) * GG + g * UU + ug);
        }

        const __nv_bfloat16* hsrc = (p ? g_hbf[1][s_split] : g_hbf[0][s_split])
                                    + (s_grow << 10) + s_half;

        // SIX independent accumulator chains
        float ahh0[4] = {0.f, 0.f, 0.f, 0.f}, ahh1[4] = {0.f, 0.f, 0.f, 0.f};
        float ahl0[4] = {0.f, 0.f, 0.f, 0.f}, ahl1[4] = {0.f, 0.f, 0.f, 0.f};
        float alh0[4] = {0.f, 0.f, 0.f, 0.f}, alh1[4] = {0.f, 0.f, 0.f, 0.f};

        // prologue: stage chunks 0,1,2 (4-buffer ring)
#pragma unroll
        for (int ck = 0; ck < 3; ck++) {
            const uint32_t dst = s_dst0 + (uint32_t)(ck * ABUF);
            const __nv_bfloat16* src = hsrc + ck * 64;
#pragma unroll
            for (int c4 = 0; c4 < 4; c4++) cp_async16(dst + c4 * 16, src + c4 * 8);
            CP_COMMIT();
        }

#pragma unroll 1
        for (int kt = 0; kt < 16; kt++) {
            if (kt <= 13)      { CP_WAIT(2); }
            else if (kt == 14) { CP_WAIT(1); }
            else               { CP_WAIT(0); }
            PAIR_BAR(bar_id);              // pair done loading kt AND done reading kt-1
            if (kt < 13) {
                const uint32_t dst = s_dst0 + (uint32_t)(((kt + 3) & 3) * ABUF);
                const __nv_bfloat16* src = hsrc + (kt + 3) * 64;
#pragma unroll
                for (int c4 = 0; c4 < 4; c4++) cp_async16(dst + c4 * 16, src + c4 * 8);
                CP_COMMIT();
            }

            const uint32_t abase = a_lane + (uint32_t)((kt & 3) * ABUF);
            const uint32_t bkoff = (uint32_t)(kt * 128);
#pragma unroll
            for (int ks = 0; ks < 4; ks++) {
                uint32_t ah[4], al[4], bh[4], bl[4];
                ldmatrix_x4(ah, abase + ks * 32);
                ldmatrix_x4(al, abase + ASPLIT + ks * 32);
                ldmatrix_x4(bh, bhi_lane + bkoff + ks * 32);
                ldmatrix_x4(bl, blo_lane + bkoff + ks * 32);
                mma_bf16(ahh0, ah, bh[0], bh[1]);
                mma_bf16(ahh1, ah, bh[2], bh[3]);
                mma_bf16(ahl0, ah, bl[0], bl[1]);
                mma_bf16(ahl1, ah, bl[2], bl[3]);
                mma_bf16(alh0, al, bh[0], bh[1]);
                mma_bf16(alh1, al, bh[2], bh[3]);
            }
        }

        // ---- combine chains ----
        float s0[4], s1[4];
#pragma unroll
        for (int i = 0; i < 4; i++) {
            s0[i] = ahh0[i] + ahl0[i] + alh0[i];
            s1[i] = ahh1[i] + ahl1[i] + alh1[i];
        }
        // exchange with neighbor lane (xor 1): even sends s1, odd sends s0
        float rv[4];
#pragma unroll
        for (int i = 0; i < 4; i++)
            rv[i] = __shfl_xor_sync(0xffffffffu, lane_odd ? s0[i] : s1[i], 1);

        // gates for my unit, rows b0g (a) and b0g+8 (b)
        float g0a = lane_odd ? rv[0] : s0[0];
        float g1a = lane_odd ? rv[1] : s0[1];
        float g2a = lane_odd ? s1[0] : rv[0];
        float g3a = lane_odd ? s1[1] : rv[1];
        float g0b = lane_odd ? rv[2] : s0[2];
        float g1b = lane_odd ? rv[3] : s0[3];
        float g2b = lane_odd ? s1[2] : rv[2];
        float g3b = lane_odd ? s1[3] : rv[3];

        // ---- cell update (i=g0, j=g1, f=g2, o=g3) ----
        float hva, hvb;
        {
            float ia = g0a + xpa[0], ja = g1a + xpa[1], fa = g2a + xpa[2], oa = g3a + xpa[3];
            float ib = g0b + xpb[0], jb = g1b + xpb[1], fb = g2b + xpb[2], ob = g3b + xpb[3];
            c.x = c.x * sigm(fa + 1.0f) + sigm(ia) * tanh_f(ja);
            c.y = c.y * sigm(fb + 1.0f) + sigm(ib) * tanh_f(jb);
            hva = tanh_f(c.x) * sigm(oa);
            hvb = tanh_f(c.y) * sigm(ob);
        }

        // ---- write split h (bf16 hi/lo, L2-visible) + fp32 output ----
        {
            __nv_bfloat16 ha_h = __float2bfloat16(hva);
            __nv_bfloat16 hb_h = __float2bfloat16(hvb);
            __nv_bfloat16 ha_l = __float2bfloat16(hva - __bfloat162float(ha_h));
            __nv_bfloat16 hb_l = __float2bfloat16(hvb - __bfloat162float(hb_h));
            const int pn = p ^ 1;
            st_u16_cg(hb_hi[pn] + (b0g << 10) + ug, ha_h);
            st_u16_cg(hb_lo[pn] + (b0g << 10) + ug, ha_l);
            st_u16_cg(hb_hi[pn] + ((b0g + 8) << 10) + ug, hb_h);
            st_u16_cg(hb_lo[pn] + ((b0g + 8) << 10) + ug, hb_l);
            out[(size_t)b0g * (TT * UU) + (size_t)step * UU + ug] = hva;
            out[(size_t)(b0g + 8) * (TT * UU) + (size_t)step * UU + ug] = hvb;
        }

        gridbar(step + 1);
    }
}

// ---------------- launch ----------------
extern "C" void kernel_launch(void* const* d_in, const int* in_sizes, int n_in,
                              void* d_out, int out_size) {
    (void)in_sizes; (void)n_in; (void)out_size;
    const float* inputs = (const float*)d_in[0];
    const float* kern   = (const float*)d_in[1];
    const float* bias   = (const float*)d_in[2];
    float* out = (float*)d_out;

    cudaFuncSetAttribute(k_recur, cudaFuncAttributeMaxDynamicSharedMemorySize, SMEM_RECUR);
    cudaFuncSetAttribute(k_xproj_mma, cudaFuncAttributeMaxDynamicSharedMemorySize, XSMEM);

    k_init<<<512, 256>>>();                                // launch 1
    k_split<<<16384 + 2048, 256>>>(inputs, kern);          // launch 2
    {
        dim3 g1(GG / 64, MM / 128);                        // (64, 512)
        k_xproj_mma<<<g1, 256, XSMEM>>>(bias);             // launch 3
    }
    k_recur<<<NCTA, 256, SMEM_RECUR>>>(kern, out);         // launch 4 <- ncu captures 4th launch
}